// round 6
// baseline (speedup 1.0000x reference)
#include <cuda_runtime.h>
#include <cstdint>

// ---------------------------------------------------------------------------
// Problem constants
// ---------------------------------------------------------------------------
#define T_  4
#define B_  4
#define C_  512
#define N_  1024          // H*W
#define NH_ 8
#define HD_ 64
#define TBAT (T_*B_)      // 16 GEMM batches
#define BCN  (B_*C_*N_)   // 2,097,152
#define EPS_ 1e-5f

typedef unsigned long long u64t;

__device__ __forceinline__ void ffma2(u64t& acc, u64t a2, u64t b2) {
    asm("fma.rn.f32x2 %0, %1, %2, %0;" : "+l"(acc) : "l"(a2), "l"(b2));
}
__device__ __forceinline__ u64t pack2(float lo, float hi) {
    u64t r;
    asm("mov.b64 %0, {%1, %2};" : "=l"(r) : "f"(lo), "f"(hi));
    return r;
}
__device__ __forceinline__ void unpack2(float& lo, float& hi, u64t p) {
    asm("mov.b64 {%0, %1}, %2;" : "=f"(lo), "=f"(hi) : "l"(p));
}
__device__ __forceinline__ uint32_t smem_u32(const void* p) {
    uint32_t a;
    asm("{ .reg .u64 t; cvta.to.shared.u64 t, %1; cvt.u32.u64 %0, t; }" : "=r"(a) : "l"(p));
    return a;
}
__device__ __forceinline__ void cp_async16(uint32_t saddr, const void* gptr) {
    asm volatile("cp.async.cg.shared.global [%0], [%1], 16;" :: "r"(saddr), "l"(gptr));
}
#define CP_COMMIT() asm volatile("cp.async.commit_group;" ::: "memory")
#define CP_WAIT1()  asm volatile("cp.async.wait_group 1;" ::: "memory")
#define CP_WAIT0()  asm volatile("cp.async.wait_group 0;" ::: "memory")

// ---------------------------------------------------------------------------
// Device scratch (static — no allocation anywhere)
// ---------------------------------------------------------------------------
__device__ float g_wt[4 * C_ * C_];    // W^T per branch: [w][c][d]
__device__ float g_xs[T_ * BCN];       // input spikes  [t,b,c,n]
__device__ float g_sq[T_ * BCN];       // q pre-act -> spikes (in-place LIF)
__device__ float g_sk[T_ * BCN];
__device__ float g_sv[T_ * BCN];
__device__ float g_y [T_ * BCN];       // o_pre scratch [t,b,c,n]
__device__ float g_os[T_ * BCN];       // attn-output spikes [t,b,c,n]
__device__ float g_kv[TBAT * NH_ * HD_ * HD_];

// ---------------------------------------------------------------------------
// Weight transpose: W[d][c] (4 branches) -> g_wt[w][c][d], smem 32x32 tiles
// ---------------------------------------------------------------------------
__global__ __launch_bounds__(256)
void prep_wt_kernel(const float* __restrict__ Wq, const float* __restrict__ Wk,
                    const float* __restrict__ Wv, const float* __restrict__ Wp)
{
    int w = blockIdx.z;
    const float* src = (w == 0) ? Wq : (w == 1) ? Wk : (w == 2) ? Wv : Wp;
    float* dst = g_wt + (size_t)w * C_ * C_;
    int d0 = blockIdx.y * 32, c0 = blockIdx.x * 32;
    int tx = threadIdx.x & 31, ty = threadIdx.x >> 5;
    __shared__ float s[32][33];
    #pragma unroll
    for (int r = 0; r < 4; r++)
        s[ty + 8 * r][tx] = src[(size_t)(d0 + ty + 8 * r) * C_ + c0 + tx];
    __syncthreads();
    #pragma unroll
    for (int r = 0; r < 4; r++)
        dst[(size_t)(c0 + ty + 8 * r) * C_ + d0 + tx] = s[tx][ty + 8 * r];
}

// ---------------------------------------------------------------------------
// Input LIF: x fp32 [t,b,c,n] -> g_xs (vth = 1.0), thread owns one (b,c,n)
// ---------------------------------------------------------------------------
__global__ __launch_bounds__(256)
void lif_in_kernel(const float* __restrict__ x)
{
    int idx = blockIdx.x * blockDim.x + threadIdx.x;
    if (idx >= BCN) return;
    float v = 0.f;
    #pragma unroll
    for (int t = 0; t < T_; t++) {
        float xv = x[(size_t)t * BCN + idx];
        v = fmaf(xv - v, 0.5f, v);
        float s = (v >= 1.0f) ? 1.f : 0.f;
        g_xs[(size_t)t * BCN + idx] = s;
        v = (v >= 1.0f) ? 0.f : v;
    }
}

// ---------------------------------------------------------------------------
// FFMA2 GEMM + BN epilogue.
//   Y[tb, d, n] = (sum_c Wt[c,d] * X[tb, c, n]) * sc[d] + sh[d]
// Block tile 128(d) x 128(n), K-tile 16, double-buffered cp.async.
// 256 threads, per-thread 8(d) x 8(n) via packed f32x2 accumulators.
// fused=1: blockIdx.z = widx*16+tb (widx 0..2 -> q/k/v); else widx=3 proj.
// ---------------------------------------------------------------------------
__global__ __launch_bounds__(256)
void gemm_f32x2_kernel(const float* __restrict__ X, int fused,
                       const float* __restrict__ qg, const float* __restrict__ qb,
                       const float* __restrict__ qm, const float* __restrict__ qv,
                       const float* __restrict__ kg, const float* __restrict__ kb,
                       const float* __restrict__ km, const float* __restrict__ kv,
                       const float* __restrict__ vg, const float* __restrict__ vb,
                       const float* __restrict__ vm, const float* __restrict__ vv,
                       const float* __restrict__ pg, const float* __restrict__ pb,
                       const float* __restrict__ pm, const float* __restrict__ pv,
                       const float* __restrict__ bias,
                       float* __restrict__ Yext)
{
    __shared__ __align__(16) float As[2][16][128];
    __shared__ __align__(16) float Bs[2][16][128];

    int zz = blockIdx.z;
    int widx, tb;
    if (fused) { widx = zz >> 4; tb = zz & 15; }
    else       { widx = 3;       tb = zz; }

    const float* gam = (widx == 0) ? qg : (widx == 1) ? kg : (widx == 2) ? vg : pg;
    const float* bet = (widx == 0) ? qb : (widx == 1) ? kb : (widx == 2) ? vb : pb;
    const float* mu  = (widx == 0) ? qm : (widx == 1) ? km : (widx == 2) ? vm : pm;
    const float* var = (widx == 0) ? qv : (widx == 1) ? kv : (widx == 2) ? vv : pv;
    float* Y = (widx == 0) ? g_sq : (widx == 1) ? g_sk : (widx == 2) ? g_sv : Yext;

    const float* Wt = g_wt + (size_t)widx * C_ * C_;
    const float* Xb = X + (size_t)tb * C_ * N_;

    int n0 = blockIdx.x * 128;
    int d0 = blockIdx.y * 128;
    int tid = threadIdx.x;
    int tm = tid >> 4;          // 0..15 -> d = d0 + tm*8
    int tn = tid & 15;          // 0..15 -> n quads at n0+tn*4 and n0+64+tn*4

    // cp.async mapping: row cp_row (k), cols cp_ch*4 and cp_ch*4+64 (float idx)
    int cp_row = tid >> 4, cp_ch = tid & 15;
    const float* gA = Wt + (size_t)cp_row * C_ + d0 + cp_ch * 4;
    const float* gB = Xb + (size_t)cp_row * N_ + n0 + cp_ch * 4;
    uint32_t sA[2], sB[2];
    #pragma unroll
    for (int s = 0; s < 2; s++) {
        sA[s] = smem_u32(&As[s][cp_row][cp_ch * 4]);
        sB[s] = smem_u32(&Bs[s][cp_row][cp_ch * 4]);
    }

    u64t acc[8][4];
    #pragma unroll
    for (int i = 0; i < 8; i++)
        #pragma unroll
        for (int j = 0; j < 4; j++) acc[i][j] = 0ull;

    // prologue: stage 0 (c0 = 0). Second chunk is +64 floats = +256 bytes.
    cp_async16(sA[0],       gA);
    cp_async16(sA[0] + 256, gA + 64);
    cp_async16(sB[0],       gB);
    cp_async16(sB[0] + 256, gB + 64);
    CP_COMMIT();

    const int NT = C_ / 16;   // 32 K-tiles
    for (int ct = 0; ct < NT; ct++) {
        // protect buffer (ct+1)&1 (read during iter ct-1) before overwriting
        __syncthreads();
        if (ct + 1 < NT) {
            int s = (ct + 1) & 1;
            size_t coff = (size_t)(ct + 1) * 16;
            cp_async16(sA[s],       gA + coff * C_);
            cp_async16(sA[s] + 256, gA + coff * C_ + 64);
            cp_async16(sB[s],       gB + coff * N_);
            cp_async16(sB[s] + 256, gB + coff * N_ + 64);
            CP_COMMIT();
            CP_WAIT1();    // pending = {ct, ct+1} -> ensures stage ct complete
        } else {
            CP_WAIT0();
        }
        __syncthreads();

        int st = ct & 1;
        #pragma unroll 4
        for (int kk = 0; kk < 16; kk++) {
            float4 a0 = *reinterpret_cast<const float4*>(&As[st][kk][tm * 8]);
            float4 a1 = *reinterpret_cast<const float4*>(&As[st][kk][tm * 8 + 4]);
            float4 b0 = *reinterpret_cast<const float4*>(&Bs[st][kk][tn * 4]);
            float4 b1 = *reinterpret_cast<const float4*>(&Bs[st][kk][64 + tn * 4]);

            u64t b2[4];
            b2[0] = pack2(b0.x, b0.y);
            b2[1] = pack2(b0.z, b0.w);
            b2[2] = pack2(b1.x, b1.y);
            b2[3] = pack2(b1.z, b1.w);

            float av[8] = {a0.x, a0.y, a0.z, a0.w, a1.x, a1.y, a1.z, a1.w};
            #pragma unroll
            for (int i = 0; i < 8; i++) {
                u64t a2 = pack2(av[i], av[i]);
                ffma2(acc[i][0], a2, b2[0]);
                ffma2(acc[i][1], a2, b2[1]);
                ffma2(acc[i][2], a2, b2[2]);
                ffma2(acc[i][3], a2, b2[3]);
            }
        }
    }

    // ---- BN epilogue + store ----
    #pragma unroll
    for (int i = 0; i < 8; i++) {
        int d = d0 + tm * 8 + i;
        float sc = gam[d] * rsqrtf(var[d] + EPS_);
        float sh = bet[d] - mu[d] * sc;
        if (!fused) sh += bias[d] * sc;
        float* Yr = Y + ((size_t)tb * C_ + d) * N_;
        float4 o0, o1;
        unpack2(o0.x, o0.y, acc[i][0]);
        unpack2(o0.z, o0.w, acc[i][1]);
        unpack2(o1.x, o1.y, acc[i][2]);
        unpack2(o1.z, o1.w, acc[i][3]);
        o0.x = o0.x * sc + sh; o0.y = o0.y * sc + sh;
        o0.z = o0.z * sc + sh; o0.w = o0.w * sc + sh;
        o1.x = o1.x * sc + sh; o1.y = o1.y * sc + sh;
        o1.z = o1.z * sc + sh; o1.w = o1.w * sc + sh;
        *reinterpret_cast<float4*>(Yr + n0 + tn * 4) = o0;
        *reinterpret_cast<float4*>(Yr + n0 + 64 + tn * 4) = o1;
    }
}

// ---------------------------------------------------------------------------
// In-place LIF over the 3 QKV pre-activation buffers (vth = 1.0)
// ---------------------------------------------------------------------------
__global__ __launch_bounds__(256)
void lif_qkv3_kernel()
{
    int gidx = blockIdx.x * blockDim.x + threadIdx.x;
    int buf = gidx / BCN;
    int idx = gidx - buf * BCN;
    float* S = (buf == 0) ? g_sq : (buf == 1) ? g_sk : g_sv;
    float v = 0.f;
    #pragma unroll
    for (int t = 0; t < T_; t++) {
        float x = S[(size_t)t * BCN + idx];
        v = fmaf(x - v, 0.5f, v);
        float s = (v >= 1.0f) ? 1.f : 0.f;
        S[(size_t)t * BCN + idx] = s;
        v = (v >= 1.0f) ? 0.f : v;
    }
}

// ---------------------------------------------------------------------------
// LIF over g_y -> g_os (vth = 0.5)
// ---------------------------------------------------------------------------
__global__ __launch_bounds__(256)
void lif_o_kernel()
{
    int idx = blockIdx.x * blockDim.x + threadIdx.x;
    if (idx >= BCN) return;
    float v = 0.f;
    #pragma unroll
    for (int t = 0; t < T_; t++) {
        float x = g_y[(size_t)t * BCN + idx];
        v = fmaf(x - v, 0.5f, v);
        float s = (v >= 0.5f) ? 1.f : 0.f;
        g_os[(size_t)t * BCN + idx] = s;
        v = (v >= 0.5f) ? 0.f : v;
    }
}

// ---------------------------------------------------------------------------
// KV[e][dd] = sum_m k[tb, h*64+e, m] * v[tb, h*64+dd, m]  (per (tb,h))
// ---------------------------------------------------------------------------
__global__ __launch_bounds__(256)
void kv_kernel()
{
    int idx = blockIdx.x;
    int tb = idx >> 3, h = idx & 7;
    const float* Kb = g_sk + (size_t)tb * C_ * N_ + (size_t)h * HD_ * N_;
    const float* Vb = g_sv + (size_t)tb * C_ * N_ + (size_t)h * HD_ * N_;
    float* KVb = g_kv + (size_t)idx * HD_ * HD_;

    __shared__ float Ks[64][65];
    __shared__ float Vs[64][65];

    int tid = threadIdx.x;
    int tx = tid & 15, ty = tid >> 4;
    float acc[4][4];
    #pragma unroll
    for (int i = 0; i < 4; i++)
        #pragma unroll
        for (int j = 0; j < 4; j++) acc[i][j] = 0.f;

    for (int m0 = 0; m0 < N_; m0 += 64) {
        int mm = tid & 63, e0 = tid >> 6;
        #pragma unroll
        for (int r = 0; r < 16; r++) {
            Ks[e0 + 4 * r][mm] = Kb[(size_t)(e0 + 4 * r) * N_ + m0 + mm];
            Vs[e0 + 4 * r][mm] = Vb[(size_t)(e0 + 4 * r) * N_ + m0 + mm];
        }
        __syncthreads();
        #pragma unroll 8
        for (int mm2 = 0; mm2 < 64; mm2++) {
            float a[4], b[4];
            #pragma unroll
            for (int i = 0; i < 4; i++) a[i] = Ks[ty * 4 + i][mm2];
            #pragma unroll
            for (int j = 0; j < 4; j++) b[j] = Vs[tx * 4 + j][mm2];
            #pragma unroll
            for (int i = 0; i < 4; i++)
                #pragma unroll
                for (int j = 0; j < 4; j++)
                    acc[i][j] = fmaf(a[i], b[j], acc[i][j]);
        }
        __syncthreads();
    }
    #pragma unroll
    for (int i = 0; i < 4; i++)
        #pragma unroll
        for (int j = 0; j < 4; j++)
            KVb[(size_t)(ty * 4 + i) * HD_ + (tx * 4 + j)] = acc[i][j];
}

// ---------------------------------------------------------------------------
// o_pre[tb, h*64+dd, n] = 0.125 * sum_e q[tb, h*64+e, n] * KV[e][dd] -> g_y
// ---------------------------------------------------------------------------
__global__ __launch_bounds__(128)
void qkv_apply_kernel()
{
    int idx = blockIdx.y;
    int tb = idx >> 3, h = idx & 7;
    int n = blockIdx.x * 128 + threadIdx.x;
    const float* Qb  = g_sq + (size_t)tb * C_ * N_ + (size_t)h * HD_ * N_;
    const float* KVb = g_kv + (size_t)idx * HD_ * HD_;
    float* Ob = g_y + (size_t)tb * C_ * N_ + (size_t)h * HD_ * N_;

    __shared__ __align__(16) float KVs[HD_ * HD_];
    for (int i = threadIdx.x; i < HD_ * HD_; i += 128) KVs[i] = KVb[i];
    __syncthreads();

    float acc[64];
    #pragma unroll
    for (int d = 0; d < 64; d++) acc[d] = 0.f;

    for (int e = 0; e < 64; e++) {
        float qv = Qb[(size_t)e * N_ + n];
        const float4* row = (const float4*)(KVs + e * 64);
        #pragma unroll
        for (int dq = 0; dq < 16; dq++) {
            float4 kvv = row[dq];
            acc[dq * 4 + 0] = fmaf(qv, kvv.x, acc[dq * 4 + 0]);
            acc[dq * 4 + 1] = fmaf(qv, kvv.y, acc[dq * 4 + 1]);
            acc[dq * 4 + 2] = fmaf(qv, kvv.z, acc[dq * 4 + 2]);
            acc[dq * 4 + 3] = fmaf(qv, kvv.w, acc[dq * 4 + 3]);
        }
    }
    #pragma unroll
    for (int d = 0; d < 64; d++)
        Ob[(size_t)d * N_ + n] = acc[d] * 0.125f;
}

// ---------------------------------------------------------------------------
// Launch
// ---------------------------------------------------------------------------
extern "C" void kernel_launch(void* const* d_in, const int* in_sizes, int n_in,
                              void* d_out, int out_size)
{
    const float* x   = (const float*)d_in[0];
    const float* Wq  = (const float*)d_in[1];
    const float* q_g = (const float*)d_in[2];
    const float* q_b = (const float*)d_in[3];
    const float* q_m = (const float*)d_in[4];
    const float* q_v = (const float*)d_in[5];
    const float* Wk  = (const float*)d_in[6];
    const float* k_g = (const float*)d_in[7];
    const float* k_b = (const float*)d_in[8];
    const float* k_m = (const float*)d_in[9];
    const float* k_v = (const float*)d_in[10];
    const float* Wv  = (const float*)d_in[11];
    const float* v_g = (const float*)d_in[12];
    const float* v_b = (const float*)d_in[13];
    const float* v_m = (const float*)d_in[14];
    const float* v_v = (const float*)d_in[15];
    const float* Wp  = (const float*)d_in[16];
    const float* bp  = (const float*)d_in[17];
    const float* p_g = (const float*)d_in[18];
    const float* p_b = (const float*)d_in[19];
    const float* p_m = (const float*)d_in[20];
    const float* p_v = (const float*)d_in[21];
    float* out = (float*)d_out;

    // 0) Weight transpose W -> Wt
    prep_wt_kernel<<<dim3(C_ / 32, C_ / 32, 4), 256>>>(Wq, Wk, Wv, Wp);

    // 1) Input LIF -> g_xs
    lif_in_kernel<<<BCN / 256, 256>>>(x);

    // 2) Fused Q/K/V GEMM (FFMA2) + BN -> g_sq/g_sk/g_sv, then in-place LIF
    gemm_f32x2_kernel<<<dim3(N_ / 128, C_ / 128, 3 * TBAT), 256>>>(
        g_xs, 1,
        q_g, q_b, q_m, q_v, k_g, k_b, k_m, k_v, v_g, v_b, v_m, v_v,
        p_g, p_b, p_m, p_v, nullptr, nullptr);
    lif_qkv3_kernel<<<(3 * BCN) / 256, 256>>>();

    // 3) Attention (exact re-association)
    kv_kernel<<<TBAT * NH_, 256>>>();
    qkv_apply_kernel<<<dim3(N_ / 128, TBAT * NH_), 128>>>();

    // 4) attn LIF (vth=0.5) -> g_os
    lif_o_kernel<<<BCN / 256, 256>>>();

    // 5) Projection GEMM (FFMA2) + bias + BN -> d_out
    gemm_f32x2_kernel<<<dim3(N_ / 128, C_ / 128, TBAT), 256>>>(
        g_os, 0,
        q_g, q_b, q_m, q_v, k_g, k_b, k_m, k_v, v_g, v_b, v_m, v_v,
        p_g, p_b, p_m, p_v, bp, out);
}

// round 7
// speedup vs baseline: 1.1321x; 1.1321x over previous
#include <cuda_runtime.h>
#include <cuda_fp16.h>
#include <cstdint>

// ---------------------------------------------------------------------------
// Problem constants
// ---------------------------------------------------------------------------
#define T_  4
#define B_  4
#define C_  512
#define N_  1024          // H*W
#define NH_ 8
#define HD_ 64
#define TBAT (T_*B_)      // 16 GEMM batches
#define BCN  (B_*C_*N_)   // 2,097,152
#define TBCN (T_*BCN)     // 8,388,608
#define EPS_ 1e-5f

__device__ __forceinline__ uint32_t smem_to_u32(const void* p) {
    uint32_t a;
    asm("{ .reg .u64 t; cvta.to.shared.u64 t, %1; cvt.u32.u64 %0, t; }" : "=r"(a) : "l"(p));
    return a;
}
__device__ __forceinline__ void ldsm_x4(uint32_t* r, uint32_t addr) {
    asm volatile("ldmatrix.sync.aligned.m8n8.x4.shared.b16 {%0,%1,%2,%3}, [%4];"
                 : "=r"(r[0]), "=r"(r[1]), "=r"(r[2]), "=r"(r[3]) : "r"(addr));
}
__device__ __forceinline__ void mma16816(float* c, const uint32_t* a, const uint32_t* b) {
    asm volatile(
        "mma.sync.aligned.m16n8k16.row.col.f32.f16.f16.f32 "
        "{%0,%1,%2,%3}, {%4,%5,%6,%7}, {%8,%9}, {%0,%1,%2,%3};"
        : "+f"(c[0]), "+f"(c[1]), "+f"(c[2]), "+f"(c[3])
        : "r"(a[0]), "r"(a[1]), "r"(a[2]), "r"(a[3]), "r"(b[0]), "r"(b[1]));
}
__device__ __forceinline__ void cp_async16(uint32_t smem_addr, const void* gptr) {
    asm volatile("cp.async.cg.shared.global [%0], [%1], 16;" :: "r"(smem_addr), "l"(gptr));
}
#define CP_COMMIT() asm volatile("cp.async.commit_group;" ::: "memory")
#define CP_WAIT2()  asm volatile("cp.async.wait_group 2;" ::: "memory")

// ---------------------------------------------------------------------------
// Device scratch (static — no allocation anywhere)
// ---------------------------------------------------------------------------
__device__ __half g_wh[4 * C_ * C_];   // fp16 hi of Wq,Wk,Wv,Wp
__device__ __half g_wl[4 * C_ * C_];   // fp16 lo (residual)
__device__ __half g_xsT[TBCN];         // input spikes, [t,b,n,c]
__device__ __half g_osT[TBCN];         // attn-output spikes, [t,b,n,c]
__device__ float  g_sq[TBCN];          // q pre-act -> spikes (in-place LIF), [t,b,d,n]
__device__ float  g_sk[TBCN];
__device__ float  g_sv[TBCN];
__device__ float  g_y [TBCN];          // o_pre scratch [t,b,n,c]
__device__ float  g_kv[TBAT * NH_ * HD_ * HD_];

// ---------------------------------------------------------------------------
// Weight prep: fp32 -> fp16 hi + fp16 lo (exact two-term split)
// ---------------------------------------------------------------------------
__global__ __launch_bounds__(256)
void prep_w_kernel(const float* __restrict__ Wq, const float* __restrict__ Wk,
                   const float* __restrict__ Wv, const float* __restrict__ Wp)
{
    int idx = blockIdx.x * blockDim.x + threadIdx.x;
    int w = idx >> 18, r = idx & ((C_ * C_) - 1);
    const float* src = (w == 0) ? Wq : (w == 1) ? Wk : (w == 2) ? Wv : Wp;
    float val = src[r];
    __half hi = __float2half_rn(val);
    __half lo = __float2half_rn(val - __half2float(hi));
    g_wh[idx] = hi;
    g_wl[idx] = lo;
}

// ---------------------------------------------------------------------------
// Input LIF with transpose: x fp32 [t,b,c,n] -> g_xsT fp16 [t,b,n,c]
// ---------------------------------------------------------------------------
__global__ __launch_bounds__(256)
void lif_in_transpose_kernel(const float* __restrict__ x)
{
    int b  = blockIdx.z;
    int c0 = blockIdx.y * 32;
    int n0 = blockIdx.x * 32;
    int tx = threadIdx.x & 31, ty = threadIdx.x >> 5;
    __shared__ float s[32][33];
    float v[4] = {0.f, 0.f, 0.f, 0.f};

    for (int t = 0; t < T_; t++) {
        #pragma unroll
        for (int r = 0; r < 4; r++) {
            int c = c0 + ty + 8 * r;
            float xv = x[(((size_t)t * B_ + b) * C_ + c) * (size_t)N_ + n0 + tx];
            float vv = v[r];
            vv = fmaf(xv - vv, 0.5f, vv);
            float sp = (vv >= 1.0f) ? 1.f : 0.f;
            v[r] = (vv >= 1.0f) ? 0.f : vv;
            s[ty + 8 * r][tx] = sp;
        }
        __syncthreads();
        #pragma unroll
        for (int r = 0; r < 4; r++) {
            int n = n0 + ty + 8 * r;
            g_xsT[(((size_t)t * B_ + b) * N_ + n) * C_ + c0 + tx] =
                __float2half(s[tx][ty + 8 * r]);
        }
        __syncthreads();
    }
}

// ---------------------------------------------------------------------------
// Pipelined HMMA GEMM + BN epilogue.
//   Y[tb, d, n] = (sum_c W[d,c] * X[tb, n, c]) * sc[d] + sh[d]
// Block 128(d) x 64(n); warp tile m32 x n32 (8 warps = 4m x 2n).
// K in 32 stages of k16; 4-stage cp.async ring; hi+lo share B frags.
// Stage layout: Ahi [kh][128][16B] (4KB) | Alo (4KB) | B [kh][64][16B] (2KB).
// ---------------------------------------------------------------------------
#define STG_BYTES 10240
#define NKS 32

__global__ __launch_bounds__(256)
void gemm_mma_kernel(const __half* __restrict__ X, int fused,
                     const float* __restrict__ qg, const float* __restrict__ qb,
                     const float* __restrict__ qm, const float* __restrict__ qv,
                     const float* __restrict__ kg, const float* __restrict__ kb,
                     const float* __restrict__ km, const float* __restrict__ kv,
                     const float* __restrict__ vg, const float* __restrict__ vb,
                     const float* __restrict__ vm, const float* __restrict__ vv,
                     const float* __restrict__ pg, const float* __restrict__ pb,
                     const float* __restrict__ pm, const float* __restrict__ pv,
                     const float* __restrict__ bias,
                     float* __restrict__ Yext)
{
    __shared__ __align__(128) char smem[4 * STG_BYTES];   // 40KB

    int zz = blockIdx.z;
    int widx, tb;
    if (fused) { widx = zz >> 4; tb = zz & 15; }
    else       { widx = 3;       tb = zz; }

    const float* gam = (widx == 0) ? qg : (widx == 1) ? kg : (widx == 2) ? vg : pg;
    const float* bet = (widx == 0) ? qb : (widx == 1) ? kb : (widx == 2) ? vb : pb;
    const float* mu  = (widx == 0) ? qm : (widx == 1) ? km : (widx == 2) ? vm : pm;
    const float* var = (widx == 0) ? qv : (widx == 1) ? kv : (widx == 2) ? vv : pv;
    float* Y = (widx == 0) ? g_sq : (widx == 1) ? g_sk : (widx == 2) ? g_sv : Yext;

    const __half* Whi = g_wh + (size_t)widx * (C_ * C_);
    const __half* Wlo = g_wl + (size_t)widx * (C_ * C_);
    const __half* Xb  = X + (size_t)tb * N_ * C_;

    int n0 = blockIdx.x * 64;
    int d0 = blockIdx.y * 128;
    int tid = threadIdx.x, lane = tid & 31, wid = tid >> 5;
    int wm = wid >> 1;        // 0..3 -> d offset wm*32
    int wn = wid & 1;         // 0..1 -> n offset wn*32

    uint32_t sbase = smem_to_u32(smem);

    // A cp.async mapping (all 256 threads): row = tid>>1, k-half = tid&1
    int a_row = tid >> 1, a_half = tid & 1;
    uint32_t a_soff = (uint32_t)(a_half * 2048 + a_row * 16);
    const __half* gA_hi = Whi + (size_t)(d0 + a_row) * C_ + a_half * 8;
    const __half* gA_lo = Wlo + (size_t)(d0 + a_row) * C_ + a_half * 8;
    // B cp.async mapping (threads 0..127): row = tid>>1 (0..63), k-half = tid&1
    int b_row = (tid & 127) >> 1, b_half = tid & 1;
    uint32_t b_soff = (uint32_t)(8192 + b_half * 1024 + b_row * 16);
    const __half* gB = Xb + (size_t)(n0 + b_row) * C_ + b_half * 8;
    bool do_b = (tid < 128);

    float acc[2][4][4];
    #pragma unroll
    for (int i = 0; i < 2; i++)
        #pragma unroll
        for (int j = 0; j < 4; j++)
            #pragma unroll
            for (int q = 0; q < 4; q++) acc[i][j][q] = 0.f;

    // ldmatrix lane addressing
    int lt = lane >> 3, lr = lane & 7;
    uint32_t a_lane = (uint32_t)(((lt >> 1) * 2048) + ((lt & 1) * 8 + lr) * 16);
    uint32_t b_lane = (uint32_t)(8192 + ((lt & 1) * 1024) + ((lt >> 1) * 8 + lr) * 16);

    // Prologue: stages 0..2
    #pragma unroll
    for (int s = 0; s < 3; s++) {
        uint32_t sb = sbase + (uint32_t)(s * STG_BYTES);
        int c0 = s * 16;
        cp_async16(sb + a_soff,        gA_hi + c0);
        cp_async16(sb + 4096 + a_soff, gA_lo + c0);
        if (do_b) cp_async16(sb + b_soff, gB + c0);
        CP_COMMIT();
    }

    for (int ks = 0; ks < NKS; ks++) {
        CP_WAIT2();
        __syncthreads();

        // issue stage ks+3 into ring slot (ks+3)&3 (its buffer was read at iter ks-1)
        int sn = ks + 3;
        if (sn < NKS) {
            uint32_t sb = sbase + (uint32_t)((sn & 3) * STG_BYTES);
            int c0 = sn * 16;
            cp_async16(sb + a_soff,        gA_hi + c0);
            cp_async16(sb + 4096 + a_soff, gA_lo + c0);
            if (do_b) cp_async16(sb + b_soff, gB + c0);
        }
        CP_COMMIT();

        uint32_t stg = sbase + (uint32_t)((ks & 3) * STG_BYTES);

        // B fragments (shared by hi and lo planes)
        uint32_t bf[2][4];
        ldsm_x4(bf[0], stg + b_lane + (uint32_t)((wn * 32) * 16));
        ldsm_x4(bf[1], stg + b_lane + (uint32_t)((wn * 32 + 16) * 16));

        uint32_t af[2][4];
        // hi plane
        #pragma unroll
        for (int i = 0; i < 2; i++)
            ldsm_x4(af[i], stg + a_lane + (uint32_t)((wm * 32 + i * 16) * 16));
        #pragma unroll
        for (int i = 0; i < 2; i++) {
            mma16816(acc[i][0], af[i], &bf[0][0]);
            mma16816(acc[i][1], af[i], &bf[0][2]);
            mma16816(acc[i][2], af[i], &bf[1][0]);
            mma16816(acc[i][3], af[i], &bf[1][2]);
        }
        // lo plane (reuse B frags)
        #pragma unroll
        for (int i = 0; i < 2; i++)
            ldsm_x4(af[i], stg + 4096 + a_lane + (uint32_t)((wm * 32 + i * 16) * 16));
        #pragma unroll
        for (int i = 0; i < 2; i++) {
            mma16816(acc[i][0], af[i], &bf[0][0]);
            mma16816(acc[i][1], af[i], &bf[0][2]);
            mma16816(acc[i][2], af[i], &bf[1][0]);
            mma16816(acc[i][3], af[i], &bf[1][2]);
        }
    }

    // ---- BN epilogue + store ----
    #pragma unroll
    for (int i = 0; i < 2; i++) {
        int dlo = d0 + wm * 32 + i * 16 + (lane >> 2);
        float sc0 = gam[dlo] * rsqrtf(var[dlo] + EPS_);
        float sh0 = bet[dlo] - mu[dlo] * sc0;
        float sc1 = gam[dlo + 8] * rsqrtf(var[dlo + 8] + EPS_);
        float sh1 = bet[dlo + 8] - mu[dlo + 8] * sc1;
        if (!fused) { sh0 += bias[dlo] * sc0; sh1 += bias[dlo + 8] * sc1; }
        float* Yr0 = Y + ((size_t)tb * C_ + dlo) * N_;
        float* Yr1 = Y + ((size_t)tb * C_ + dlo + 8) * N_;
        #pragma unroll
        for (int j = 0; j < 4; j++) {
            int n = n0 + wn * 32 + j * 8 + (lane & 3) * 2;
            float2 v0, v1;
            v0.x = acc[i][j][0] * sc0 + sh0;
            v0.y = acc[i][j][1] * sc0 + sh0;
            v1.x = acc[i][j][2] * sc1 + sh1;
            v1.y = acc[i][j][3] * sc1 + sh1;
            *reinterpret_cast<float2*>(Yr0 + n) = v0;
            *reinterpret_cast<float2*>(Yr1 + n) = v1;
        }
    }
}

// ---------------------------------------------------------------------------
// In-place LIF over the 3 QKV pre-activation buffers (vth = 1.0)
// ---------------------------------------------------------------------------
__global__ __launch_bounds__(256)
void lif_qkv3_kernel()
{
    int gidx = blockIdx.x * blockDim.x + threadIdx.x;
    int buf = gidx / BCN;
    int idx = gidx - buf * BCN;
    float* S = (buf == 0) ? g_sq : (buf == 1) ? g_sk : g_sv;
    float v = 0.f;
    #pragma unroll
    for (int t = 0; t < T_; t++) {
        float x = S[(size_t)t * BCN + idx];
        v = fmaf(x - v, 0.5f, v);
        float s = (v >= 1.0f) ? 1.f : 0.f;
        S[(size_t)t * BCN + idx] = s;
        v = (v >= 1.0f) ? 0.f : v;
    }
}

// ---------------------------------------------------------------------------
// LIF over g_y [t,b,n,c] fp32 -> g_osT fp16 (vth=0.5)
// ---------------------------------------------------------------------------
__global__ __launch_bounds__(256)
void lif_o_kernel()
{
    int idx = blockIdx.x * blockDim.x + threadIdx.x;
    if (idx >= BCN) return;
    float v = 0.f;
    #pragma unroll
    for (int t = 0; t < T_; t++) {
        float x = g_y[(size_t)t * BCN + idx];
        v = fmaf(x - v, 0.5f, v);
        float s = (v >= 0.5f) ? 1.f : 0.f;
        g_osT[(size_t)t * BCN + idx] = __float2half(s);
        v = (v >= 0.5f) ? 0.f : v;
    }
}

// ---------------------------------------------------------------------------
// KV[e][dd] = sum_m k[tb, h*64+e, m] * v[tb, h*64+dd, m]  (per (tb,h))
// ---------------------------------------------------------------------------
__global__ __launch_bounds__(256)
void kv_kernel()
{
    int idx = blockIdx.x;
    int tb = idx >> 3, h = idx & 7;
    const float* Kb = g_sk + (size_t)tb * C_ * N_ + (size_t)h * HD_ * N_;
    const float* Vb = g_sv + (size_t)tb * C_ * N_ + (size_t)h * HD_ * N_;
    float* KVb = g_kv + (size_t)idx * HD_ * HD_;

    __shared__ float Ks[64][65];
    __shared__ float Vs[64][65];

    int tid = threadIdx.x;
    int tx = tid & 15, ty = tid >> 4;
    float acc[4][4];
    #pragma unroll
    for (int i = 0; i < 4; i++)
        #pragma unroll
        for (int j = 0; j < 4; j++) acc[i][j] = 0.f;

    for (int m0 = 0; m0 < N_; m0 += 64) {
        int mm = tid & 63, e0 = tid >> 6;
        #pragma unroll
        for (int r = 0; r < 16; r++) {
            Ks[e0 + 4 * r][mm] = Kb[(size_t)(e0 + 4 * r) * N_ + m0 + mm];
            Vs[e0 + 4 * r][mm] = Vb[(size_t)(e0 + 4 * r) * N_ + m0 + mm];
        }
        __syncthreads();
        #pragma unroll 8
        for (int mm2 = 0; mm2 < 64; mm2++) {
            float a[4], b[4];
            #pragma unroll
            for (int i = 0; i < 4; i++) a[i] = Ks[ty * 4 + i][mm2];
            #pragma unroll
            for (int j = 0; j < 4; j++) b[j] = Vs[tx * 4 + j][mm2];
            #pragma unroll
            for (int i = 0; i < 4; i++)
                #pragma unroll
                for (int j = 0; j < 4; j++)
                    acc[i][j] = fmaf(a[i], b[j], acc[i][j]);
        }
        __syncthreads();
    }
    #pragma unroll
    for (int i = 0; i < 4; i++)
        #pragma unroll
        for (int j = 0; j < 4; j++)
            KVb[(size_t)(ty * 4 + i) * HD_ + (tx * 4 + j)] = acc[i][j];
}

// ---------------------------------------------------------------------------
// o_pre[tb, n, h*64+dd] = 0.125 * sum_e q[tb, h*64+e, n] * KV[e][dd]
// Writes transposed layout [t,b,n,c] into g_y.
// ---------------------------------------------------------------------------
__global__ __launch_bounds__(128)
void qkv_apply_kernel()
{
    int idx = blockIdx.y;
    int tb = idx >> 3, h = idx & 7;
    int n = blockIdx.x * 128 + threadIdx.x;
    const float* Qb  = g_sq + (size_t)tb * C_ * N_ + (size_t)h * HD_ * N_;
    const float* KVb = g_kv + (size_t)idx * HD_ * HD_;

    __shared__ __align__(16) float KVs[HD_ * HD_];
    for (int i = threadIdx.x; i < HD_ * HD_; i += 128) KVs[i] = KVb[i];
    __syncthreads();

    float acc[64];
    #pragma unroll
    for (int d = 0; d < 64; d++) acc[d] = 0.f;

    for (int e = 0; e < 64; e++) {
        float qv = Qb[(size_t)e * N_ + n];
        const float4* row = (const float4*)(KVs + e * 64);
        #pragma unroll
        for (int dq = 0; dq < 16; dq++) {
            float4 kvv = row[dq];
            acc[dq * 4 + 0] = fmaf(qv, kvv.x, acc[dq * 4 + 0]);
            acc[dq * 4 + 1] = fmaf(qv, kvv.y, acc[dq * 4 + 1]);
            acc[dq * 4 + 2] = fmaf(qv, kvv.z, acc[dq * 4 + 2]);
            acc[dq * 4 + 3] = fmaf(qv, kvv.w, acc[dq * 4 + 3]);
        }
    }
    float* orow = g_y + ((size_t)tb * N_ + n) * C_ + h * HD_;
    #pragma unroll
    for (int q = 0; q < 16; q++) {
        float4 o;
        o.x = acc[q * 4 + 0] * 0.125f;
        o.y = acc[q * 4 + 1] * 0.125f;
        o.z = acc[q * 4 + 2] * 0.125f;
        o.w = acc[q * 4 + 3] * 0.125f;
        ((float4*)orow)[q] = o;
    }
}

// ---------------------------------------------------------------------------
// Launch
// ---------------------------------------------------------------------------
extern "C" void kernel_launch(void* const* d_in, const int* in_sizes, int n_in,
                              void* d_out, int out_size)
{
    const float* x   = (const float*)d_in[0];
    const float* Wq  = (const float*)d_in[1];
    const float* q_g = (const float*)d_in[2];
    const float* q_b = (const float*)d_in[3];
    const float* q_m = (const float*)d_in[4];
    const float* q_v = (const float*)d_in[5];
    const float* Wk  = (const float*)d_in[6];
    const float* k_g = (const float*)d_in[7];
    const float* k_b = (const float*)d_in[8];
    const float* k_m = (const float*)d_in[9];
    const float* k_v = (const float*)d_in[10];
    const float* Wv  = (const float*)d_in[11];
    const float* v_g = (const float*)d_in[12];
    const float* v_b = (const float*)d_in[13];
    const float* v_m = (const float*)d_in[14];
    const float* v_v = (const float*)d_in[15];
    const float* Wp  = (const float*)d_in[16];
    const float* bp  = (const float*)d_in[17];
    const float* p_g = (const float*)d_in[18];
    const float* p_b = (const float*)d_in[19];
    const float* p_m = (const float*)d_in[20];
    const float* p_v = (const float*)d_in[21];
    float* out = (float*)d_out;

    dim3 lif_in_grid(N_ / 32, C_ / 32, B_);

    // 0) Weight split fp32 -> fp16 hi/lo
    prep_w_kernel<<<(4 * C_ * C_) / 256, 256>>>(Wq, Wk, Wv, Wp);

    // 1) Input LIF -> transposed fp16 spikes [t,b,n,c]
    lif_in_transpose_kernel<<<lif_in_grid, 256>>>(x);

    // 2) Fused Q/K/V GEMM (pipelined HMMA) + BN, then in-place LIF
    gemm_mma_kernel<<<dim3(N_ / 64, C_ / 128, 3 * TBAT), 256>>>(
        g_xsT, 1,
        q_g, q_b, q_m, q_v, k_g, k_b, k_m, k_v, v_g, v_b, v_m, v_v,
        p_g, p_b, p_m, p_v, nullptr, nullptr);
    lif_qkv3_kernel<<<(3 * BCN) / 256, 256>>>();

    // 3) Attention (exact re-association)
    kv_kernel<<<TBAT * NH_, 256>>>();
    qkv_apply_kernel<<<dim3(N_ / 128, TBAT * NH_), 128>>>();

    // 4) attn LIF (vth=0.5) -> transposed fp16 spikes g_osT
    lif_o_kernel<<<BCN / 256, 256>>>();

    // 5) Projection GEMM (pipelined HMMA) + bias + BN -> d_out
    gemm_mma_kernel<<<dim3(N_ / 64, C_ / 128, TBAT), 256>>>(
        g_osT, 0,
        q_g, q_b, q_m, q_v, k_g, k_b, k_m, k_v, v_g, v_b, v_m, v_v,
        p_g, p_b, p_m, p_v, bp, out);
}

// round 8
// speedup vs baseline: 11.2925x; 9.9751x over previous
#include <cuda_runtime.h>
#include <cstdint>

// ---------------------------------------------------------------------------
// Problem constants
// ---------------------------------------------------------------------------
#define T_  4
#define B_  4
#define C_  512
#define N_  1024          // H*W
#define NH_ 8
#define HD_ 64
#define TBAT (T_*B_)      // 16 GEMM batches
#define BCN  (B_*C_*N_)   // 2,097,152
#define CC   (C_*C_)
#define EPS_ 1e-5f

// ---------------------------------------------------------------------------
// Device scratch (static — no allocation anywhere)
// All activation tensors in [tb][n][c] layout (c contiguous).
// ---------------------------------------------------------------------------
__device__ float g_wt[4 * CC];        // W^T per branch: [w][c][d]
__device__ float g_xs[T_ * BCN];      // input spikes   [tb][n][c]
__device__ float g_sq[T_ * BCN];      // q pre-act -> spikes (in-place LIF)
__device__ float g_sk[T_ * BCN];
__device__ float g_sv[T_ * BCN];
__device__ float g_y [T_ * BCN];      // o_pre scratch  [tb][n][c]
__device__ float g_os[T_ * BCN];      // attn-out spikes [tb][n][c]
__device__ float g_kv[TBAT * NH_ * HD_ * HD_];   // [tb*8+h][e][dd]

// ---------------------------------------------------------------------------
// Weight transpose (one branch per launch): W[d][c] -> g_wt[w][c][d]
// ---------------------------------------------------------------------------
__global__ __launch_bounds__(256)
void prep_wt_kernel(const float* __restrict__ src, int w)
{
    float* dst = g_wt + (size_t)w * CC;
    int d0 = blockIdx.y * 32, c0 = blockIdx.x * 32;
    int tx = threadIdx.x & 31, ty = threadIdx.x >> 5;
    __shared__ float s[32][33];
    #pragma unroll
    for (int r = 0; r < 4; r++)
        s[ty + 8 * r][tx] = src[(size_t)(d0 + ty + 8 * r) * C_ + c0 + tx];
    __syncthreads();
    #pragma unroll
    for (int r = 0; r < 4; r++)
        dst[(size_t)(c0 + ty + 8 * r) * C_ + d0 + tx] = s[tx][ty + 8 * r];
}

// ---------------------------------------------------------------------------
// Input LIF with transpose: x fp32 [t,b,c,n] -> g_xs fp32 [t,b,n,c], vth=1
// ---------------------------------------------------------------------------
__global__ __launch_bounds__(256)
void lif_in_transpose_kernel(const float* __restrict__ x)
{
    int b  = blockIdx.z;
    int c0 = blockIdx.y * 32;
    int n0 = blockIdx.x * 32;
    int tx = threadIdx.x & 31, ty = threadIdx.x >> 5;
    __shared__ float s[32][33];
    float v[4] = {0.f, 0.f, 0.f, 0.f};

    for (int t = 0; t < T_; t++) {
        #pragma unroll
        for (int r = 0; r < 4; r++) {
            int c = c0 + ty + 8 * r;
            float xv = x[(((size_t)t * B_ + b) * C_ + c) * (size_t)N_ + n0 + tx];
            float vv = v[r];
            vv = fmaf(xv - vv, 0.5f, vv);
            float sp = (vv >= 1.0f) ? 1.f : 0.f;
            v[r] = (vv >= 1.0f) ? 0.f : vv;
            s[ty + 8 * r][tx] = sp;
        }
        __syncthreads();
        #pragma unroll
        for (int r = 0; r < 4; r++) {
            int n = n0 + ty + 8 * r;
            g_xs[(((size_t)t * B_ + b) * N_ + n) * C_ + c0 + tx] = s[tx][ty + 8 * r];
        }
        __syncthreads();
    }
}

// ---------------------------------------------------------------------------
// Deterministic active-channel list build (ballot + popc prefix, ascending c)
// 128 threads. Returns count via smem. Requires spikes exactly 0.0 / 1.0.
// ---------------------------------------------------------------------------
__device__ __forceinline__ int build_list(const float* __restrict__ row,
                                          uint16_t* list, uint32_t* maskw,
                                          int* basew, int* cntp)
{
    int tid = threadIdx.x, warp = tid >> 5, lane = tid & 31;
    #pragma unroll
    for (int ci = warp; ci < 16; ci += 4) {
        float sv = row[ci * 32 + lane];
        uint32_t m = __ballot_sync(0xffffffffu, sv != 0.f);
        if (lane == 0) maskw[ci] = m;
    }
    __syncthreads();
    if (tid == 0) {
        int s = 0;
        #pragma unroll
        for (int ci = 0; ci < 16; ci++) { basew[ci] = s; s += __popc(maskw[ci]); }
        *cntp = s;
    }
    __syncthreads();
    #pragma unroll
    for (int ci = warp; ci < 16; ci += 4) {
        uint32_t m = maskw[ci];
        if (m & (1u << lane))
            list[basew[ci] + __popc(m & ((1u << lane) - 1u))] = (uint16_t)(ci * 32 + lane);
    }
    __syncthreads();
    return *cntp;
}

// ---------------------------------------------------------------------------
// Fused Q/K/V activity-gathered GEMM + BN.
//   Yw[tb][n][d] = (sum_{c active} WwT[c][d]) * scw[d] + shw[d]
// Block = one (tb, n); 128 threads, thread owns d = 4*tid .. 4*tid+3.
// ---------------------------------------------------------------------------
__global__ __launch_bounds__(128)
void gather_qkv_kernel(const float* __restrict__ qg, const float* __restrict__ qb,
                       const float* __restrict__ qm, const float* __restrict__ qv,
                       const float* __restrict__ kg, const float* __restrict__ kb,
                       const float* __restrict__ km, const float* __restrict__ kv,
                       const float* __restrict__ vg, const float* __restrict__ vb,
                       const float* __restrict__ vm, const float* __restrict__ vv)
{
    int tb = blockIdx.y, n = blockIdx.x;
    int tid = threadIdx.x;
    const float* xrow = g_xs + ((size_t)tb * N_ + n) * C_;

    __shared__ uint16_t list[C_];
    __shared__ uint32_t maskw[16];
    __shared__ int basew[16];
    __shared__ int cnt;

    int count = build_list(xrow, list, maskw, basew, &cnt);

    const float4* Wq4 = (const float4*)(g_wt + 0 * (size_t)CC);
    const float4* Wk4 = (const float4*)(g_wt + 1 * (size_t)CC);
    const float4* Wv4 = (const float4*)(g_wt + 2 * (size_t)CC);

    float4 aq = {0.f, 0.f, 0.f, 0.f}, ak = aq, av = aq;
    for (int i = 0; i < count; i++) {
        int c = list[i];
        float4 wq = Wq4[(size_t)c * 128 + tid];
        float4 wk = Wk4[(size_t)c * 128 + tid];
        float4 wv = Wv4[(size_t)c * 128 + tid];
        aq.x += wq.x; aq.y += wq.y; aq.z += wq.z; aq.w += wq.w;
        ak.x += wk.x; ak.y += wk.y; ak.z += wk.z; ak.w += wk.w;
        av.x += wv.x; av.y += wv.y; av.z += wv.z; av.w += wv.w;
    }

    size_t orow = ((size_t)tb * N_ + n) * C_;
    // BN per branch (vectorized over thread's 4 d's)
    {
        float4 g = ((const float4*)qg)[tid], b = ((const float4*)qb)[tid];
        float4 m = ((const float4*)qm)[tid], v = ((const float4*)qv)[tid];
        float4 o;
        o.x = (aq.x - m.x) * (g.x * rsqrtf(v.x + EPS_)) + b.x;
        o.y = (aq.y - m.y) * (g.y * rsqrtf(v.y + EPS_)) + b.y;
        o.z = (aq.z - m.z) * (g.z * rsqrtf(v.z + EPS_)) + b.z;
        o.w = (aq.w - m.w) * (g.w * rsqrtf(v.w + EPS_)) + b.w;
        ((float4*)(g_sq + orow))[tid] = o;
    }
    {
        float4 g = ((const float4*)kg)[tid], b = ((const float4*)kb)[tid];
        float4 m = ((const float4*)km)[tid], v = ((const float4*)kv)[tid];
        float4 o;
        o.x = (ak.x - m.x) * (g.x * rsqrtf(v.x + EPS_)) + b.x;
        o.y = (ak.y - m.y) * (g.y * rsqrtf(v.y + EPS_)) + b.y;
        o.z = (ak.z - m.z) * (g.z * rsqrtf(v.z + EPS_)) + b.z;
        o.w = (ak.w - m.w) * (g.w * rsqrtf(v.w + EPS_)) + b.w;
        ((float4*)(g_sk + orow))[tid] = o;
    }
    {
        float4 g = ((const float4*)vg)[tid], b = ((const float4*)vb)[tid];
        float4 m = ((const float4*)vm)[tid], v = ((const float4*)vv)[tid];
        float4 o;
        o.x = (av.x - m.x) * (g.x * rsqrtf(v.x + EPS_)) + b.x;
        o.y = (av.y - m.y) * (g.y * rsqrtf(v.y + EPS_)) + b.y;
        o.z = (av.z - m.z) * (g.z * rsqrtf(v.z + EPS_)) + b.z;
        o.w = (av.w - m.w) * (g.w * rsqrtf(v.w + EPS_)) + b.w;
        ((float4*)(g_sv + orow))[tid] = o;
    }
}

// ---------------------------------------------------------------------------
// Projection activity-gathered GEMM + bias + BN -> final output [tb][d][n]
// ---------------------------------------------------------------------------
__global__ __launch_bounds__(128)
void gather_proj_kernel(const float* __restrict__ bp,
                        const float* __restrict__ pg, const float* __restrict__ pb,
                        const float* __restrict__ pm, const float* __restrict__ pv,
                        float* __restrict__ out)
{
    int tb = blockIdx.y, n = blockIdx.x;
    int tid = threadIdx.x;
    const float* orow_in = g_os + ((size_t)tb * N_ + n) * C_;

    __shared__ uint16_t list[C_];
    __shared__ uint32_t maskw[16];
    __shared__ int basew[16];
    __shared__ int cnt;

    int count = build_list(orow_in, list, maskw, basew, &cnt);

    const float4* Wp4 = (const float4*)(g_wt + 3 * (size_t)CC);
    float4 ap = {0.f, 0.f, 0.f, 0.f};
    for (int i = 0; i < count; i++) {
        int c = list[i];
        float4 wp = Wp4[(size_t)c * 128 + tid];
        ap.x += wp.x; ap.y += wp.y; ap.z += wp.z; ap.w += wp.w;
    }

    float4 bi = ((const float4*)bp)[tid];
    float4 g = ((const float4*)pg)[tid], b = ((const float4*)pb)[tid];
    float4 m = ((const float4*)pm)[tid], v = ((const float4*)pv)[tid];
    float o0 = (ap.x + bi.x - m.x) * (g.x * rsqrtf(v.x + EPS_)) + b.x;
    float o1 = (ap.y + bi.y - m.y) * (g.y * rsqrtf(v.y + EPS_)) + b.y;
    float o2 = (ap.z + bi.z - m.z) * (g.z * rsqrtf(v.z + EPS_)) + b.z;
    float o3 = (ap.w + bi.w - m.w) * (g.w * rsqrtf(v.w + EPS_)) + b.w;

    // scatter to [tb][d][n]
    float* ob = out + (size_t)tb * C_ * N_ + n;
    ob[(size_t)(4 * tid + 0) * N_] = o0;
    ob[(size_t)(4 * tid + 1) * N_] = o1;
    ob[(size_t)(4 * tid + 2) * N_] = o2;
    ob[(size_t)(4 * tid + 3) * N_] = o3;
}

// ---------------------------------------------------------------------------
// In-place LIF over the 3 QKV pre-activation buffers (vth = 1.0)
// Layout-agnostic: t-stride is BCN.
// ---------------------------------------------------------------------------
__global__ __launch_bounds__(256)
void lif_qkv3_kernel()
{
    int gidx = blockIdx.x * blockDim.x + threadIdx.x;
    int buf = gidx / BCN;
    int idx = gidx - buf * BCN;
    float* S = (buf == 0) ? g_sq : (buf == 1) ? g_sk : g_sv;
    float v = 0.f;
    #pragma unroll
    for (int t = 0; t < T_; t++) {
        float x = S[(size_t)t * BCN + idx];
        v = fmaf(x - v, 0.5f, v);
        float s = (v >= 1.0f) ? 1.f : 0.f;
        S[(size_t)t * BCN + idx] = s;
        v = (v >= 1.0f) ? 0.f : v;
    }
}

// ---------------------------------------------------------------------------
// LIF over g_y -> g_os (vth = 0.5), [tb][n][c] passthrough
// ---------------------------------------------------------------------------
__global__ __launch_bounds__(256)
void lif_o_kernel()
{
    int idx = blockIdx.x * blockDim.x + threadIdx.x;
    if (idx >= BCN) return;
    float v = 0.f;
    #pragma unroll
    for (int t = 0; t < T_; t++) {
        float x = g_y[(size_t)t * BCN + idx];
        v = fmaf(x - v, 0.5f, v);
        float s = (v >= 0.5f) ? 1.f : 0.f;
        g_os[(size_t)t * BCN + idx] = s;
        v = (v >= 0.5f) ? 0.f : v;
    }
}

// ---------------------------------------------------------------------------
// KV[e][dd] = sum_n k[tb][n][h64+e] * v[tb][n][h64+dd]   per (tb,h)
// Inputs in [n][c] layout; smem tiles transposed to [e][n].
// ---------------------------------------------------------------------------
__global__ __launch_bounds__(256)
void kv_kernel()
{
    int idx = blockIdx.x;                   // tb*8 + h
    int tb = idx >> 3, h = idx & 7;
    const float* Kb = g_sk + (size_t)tb * N_ * C_ + h * HD_;
    const float* Vb = g_sv + (size_t)tb * N_ * C_ + h * HD_;
    float* KVb = g_kv + (size_t)idx * HD_ * HD_;

    __shared__ float Ks[64][65];
    __shared__ float Vs[64][65];

    int tid = threadIdx.x;
    int tx = tid & 15, ty = tid >> 4;
    int le = tid & 63, lr = tid >> 6;       // load mapping: e = le, n-row += lr
    float acc[4][4];
    #pragma unroll
    for (int i = 0; i < 4; i++)
        #pragma unroll
        for (int j = 0; j < 4; j++) acc[i][j] = 0.f;

    for (int n0 = 0; n0 < N_; n0 += 64) {
        #pragma unroll
        for (int r = 0; r < 16; r++) {
            int nn = lr + 4 * r;
            Ks[le][nn] = Kb[(size_t)(n0 + nn) * C_ + le];
            Vs[le][nn] = Vb[(size_t)(n0 + nn) * C_ + le];
        }
        __syncthreads();
        #pragma unroll 8
        for (int nn = 0; nn < 64; nn++) {
            float a[4], b[4];
            #pragma unroll
            for (int i = 0; i < 4; i++) a[i] = Ks[ty * 4 + i][nn];
            #pragma unroll
            for (int j = 0; j < 4; j++) b[j] = Vs[tx * 4 + j][nn];
            #pragma unroll
            for (int i = 0; i < 4; i++)
                #pragma unroll
                for (int j = 0; j < 4; j++)
                    acc[i][j] = fmaf(a[i], b[j], acc[i][j]);
        }
        __syncthreads();
    }
    #pragma unroll
    for (int i = 0; i < 4; i++)
        #pragma unroll
        for (int j = 0; j < 4; j++)
            KVb[(size_t)(ty * 4 + i) * HD_ + (tx * 4 + j)] = acc[i][j];
}

// ---------------------------------------------------------------------------
// o_pre[tb][n][h64+dd] = 0.125 * sum_e q[tb][n][h64+e] * KV[e][dd] -> g_y
// Thread = one n; q row contiguous; output row contiguous.
// ---------------------------------------------------------------------------
__global__ __launch_bounds__(128)
void qkv_apply_kernel()
{
    int idx = blockIdx.y;                   // tb*8 + h
    int tb = idx >> 3, h = idx & 7;
    int n = blockIdx.x * 128 + threadIdx.x;
    const float* qrow = g_sq + ((size_t)tb * N_ + n) * C_ + h * HD_;
    const float* KVb = g_kv + (size_t)idx * HD_ * HD_;
    float* orow = g_y + ((size_t)tb * N_ + n) * C_ + h * HD_;

    __shared__ __align__(16) float KVs[HD_ * HD_];
    for (int i = threadIdx.x; i < HD_ * HD_; i += 128) KVs[i] = KVb[i];
    __syncthreads();

    float acc[64];
    #pragma unroll
    for (int d = 0; d < 64; d++) acc[d] = 0.f;

    #pragma unroll 4
    for (int e4 = 0; e4 < 16; e4++) {
        float4 q4 = ((const float4*)qrow)[e4];
        float qs[4] = {q4.x, q4.y, q4.z, q4.w};
        #pragma unroll
        for (int s = 0; s < 4; s++) {
            float qv = qs[s];
            if (qv != 0.f) {                 // spikes are 0/1 -> skip zeros
                const float4* row = (const float4*)(KVs + (e4 * 4 + s) * 64);
                #pragma unroll
                for (int dq = 0; dq < 16; dq++) {
                    float4 kvv = row[dq];
                    acc[dq * 4 + 0] += kvv.x;
                    acc[dq * 4 + 1] += kvv.y;
                    acc[dq * 4 + 2] += kvv.z;
                    acc[dq * 4 + 3] += kvv.w;
                }
            }
        }
    }
    #pragma unroll
    for (int q = 0; q < 16; q++) {
        float4 o;
        o.x = acc[q * 4 + 0] * 0.125f;
        o.y = acc[q * 4 + 1] * 0.125f;
        o.z = acc[q * 4 + 2] * 0.125f;
        o.w = acc[q * 4 + 3] * 0.125f;
        ((float4*)orow)[q] = o;
    }
}

// ---------------------------------------------------------------------------
// Launch (prep split into 4 launches so ncu -s 5 lands on gather_qkv)
// ---------------------------------------------------------------------------
extern "C" void kernel_launch(void* const* d_in, const int* in_sizes, int n_in,
                              void* d_out, int out_size)
{
    const float* x   = (const float*)d_in[0];
    const float* Wq  = (const float*)d_in[1];
    const float* q_g = (const float*)d_in[2];
    const float* q_b = (const float*)d_in[3];
    const float* q_m = (const float*)d_in[4];
    const float* q_v = (const float*)d_in[5];
    const float* Wk  = (const float*)d_in[6];
    const float* k_g = (const float*)d_in[7];
    const float* k_b = (const float*)d_in[8];
    const float* k_m = (const float*)d_in[9];
    const float* k_v = (const float*)d_in[10];
    const float* Wv  = (const float*)d_in[11];
    const float* v_g = (const float*)d_in[12];
    const float* v_b = (const float*)d_in[13];
    const float* v_m = (const float*)d_in[14];
    const float* v_v = (const float*)d_in[15];
    const float* Wp  = (const float*)d_in[16];
    const float* bp  = (const float*)d_in[17];
    const float* p_g = (const float*)d_in[18];
    const float* p_b = (const float*)d_in[19];
    const float* p_m = (const float*)d_in[20];
    const float* p_v = (const float*)d_in[21];
    float* out = (float*)d_out;

    dim3 wt_grid(C_ / 32, C_ / 32);
    dim3 lif_in_grid(N_ / 32, C_ / 32, B_);
    dim3 gather_grid(N_, TBAT);

    // launches 0-3: weight transposes
    prep_wt_kernel<<<wt_grid, 256>>>(Wq, 0);
    prep_wt_kernel<<<wt_grid, 256>>>(Wk, 1);
    prep_wt_kernel<<<wt_grid, 256>>>(Wv, 2);
    prep_wt_kernel<<<wt_grid, 256>>>(Wp, 3);

    // launch 4: input LIF -> [tb][n][c] spikes
    lif_in_transpose_kernel<<<lif_in_grid, 256>>>(x);

    // launch 5: fused QKV gather-GEMM + BN  (ncu profiles this one)
    gather_qkv_kernel<<<gather_grid, 128>>>(
        q_g, q_b, q_m, q_v, k_g, k_b, k_m, k_v, v_g, v_b, v_m, v_v);

    // launch 6: in-place LIF q/k/v
    lif_qkv3_kernel<<<(3 * BCN) / 256, 256>>>();

    // launch 7-8: attention (exact re-association)
    kv_kernel<<<TBAT * NH_, 256>>>();
    qkv_apply_kernel<<<dim3(N_ / 128, TBAT * NH_), 128>>>();

    // launch 9: attn LIF (vth=0.5)
    lif_o_kernel<<<BCN / 256, 256>>>();

    // launch 10: projection gather-GEMM + bias + BN -> out
    gather_proj_kernel<<<gather_grid, 128>>>(bp, p_g, p_b, p_m, p_v, out);
}

// round 9
// speedup vs baseline: 13.9556x; 1.2358x over previous
#include <cuda_runtime.h>
#include <cstdint>

// ---------------------------------------------------------------------------
// Problem constants
// ---------------------------------------------------------------------------
#define T_  4
#define B_  4
#define C_  512
#define N_  1024          // H*W
#define NH_ 8
#define HD_ 64
#define TBAT (T_*B_)
#define BCN  (B_*C_*N_)   // 2,097,152
#define CC   (C_*C_)
#define EPS_ 1e-5f

// ---------------------------------------------------------------------------
// Device scratch (static — no allocation anywhere)
// Activations in [tb][n][c] layout (c contiguous) unless noted.
// ---------------------------------------------------------------------------
__device__ float g_wt[4 * CC];        // W^T per branch: [w][c][d]
__device__ float g_xs[T_ * BCN];      // input spikes   [tb][n][c]
__device__ float g_sq[T_ * BCN];      // q spikes       [tb][n][c]
__device__ float g_sk[T_ * BCN];
__device__ float g_sv[T_ * BCN];
__device__ float g_y [T_ * BCN];      // o_pre scratch  [tb][n][c]
__device__ float g_ot[T_ * BCN];      // proj output    [tb][n][c] (pre-transpose)
__device__ float g_kv[TBAT * NH_ * HD_ * HD_];   // [tb*8+h][e][dd]

// ---------------------------------------------------------------------------
// Weight transpose (all 4 branches, one launch): W[d][c] -> g_wt[w][c][d]
// ---------------------------------------------------------------------------
__global__ __launch_bounds__(256)
void prep_wt_kernel(const float* __restrict__ Wq, const float* __restrict__ Wk,
                    const float* __restrict__ Wv, const float* __restrict__ Wp)
{
    int w = blockIdx.z;
    const float* src = (w == 0) ? Wq : (w == 1) ? Wk : (w == 2) ? Wv : Wp;
    float* dst = g_wt + (size_t)w * CC;
    int d0 = blockIdx.y * 32, c0 = blockIdx.x * 32;
    int tx = threadIdx.x & 31, ty = threadIdx.x >> 5;
    __shared__ float s[32][33];
    #pragma unroll
    for (int r = 0; r < 4; r++)
        s[ty + 8 * r][tx] = src[(size_t)(d0 + ty + 8 * r) * C_ + c0 + tx];
    __syncthreads();
    #pragma unroll
    for (int r = 0; r < 4; r++)
        dst[(size_t)(c0 + ty + 8 * r) * C_ + d0 + tx] = s[tx][ty + 8 * r];
}

// ---------------------------------------------------------------------------
// Input LIF with transpose: x fp32 [t,b,c,n] -> g_xs fp32 [t,b,n,c], vth=1
// ---------------------------------------------------------------------------
__global__ __launch_bounds__(256)
void lif_in_transpose_kernel(const float* __restrict__ x)
{
    int b  = blockIdx.z;
    int c0 = blockIdx.y * 32;
    int n0 = blockIdx.x * 32;
    int tx = threadIdx.x & 31, ty = threadIdx.x >> 5;
    __shared__ float s[32][33];
    float v[4] = {0.f, 0.f, 0.f, 0.f};

    for (int t = 0; t < T_; t++) {
        #pragma unroll
        for (int r = 0; r < 4; r++) {
            int c = c0 + ty + 8 * r;
            float xv = x[(((size_t)t * B_ + b) * C_ + c) * (size_t)N_ + n0 + tx];
            float vv = v[r];
            vv = fmaf(xv - vv, 0.5f, vv);
            float sp = (vv >= 1.0f) ? 1.f : 0.f;
            v[r] = (vv >= 1.0f) ? 0.f : vv;
            s[ty + 8 * r][tx] = sp;
        }
        __syncthreads();
        #pragma unroll
        for (int r = 0; r < 4; r++) {
            int n = n0 + ty + 8 * r;
            g_xs[(((size_t)t * B_ + b) * N_ + n) * C_ + c0 + tx] = s[tx][ty + 8 * r];
        }
        __syncthreads();
    }
}

// ---------------------------------------------------------------------------
// Deterministic active-channel list build (ballot + popc prefix, ascending c)
// 128 threads. Spikes must be exactly 0.0 / 1.0.
// NOTE on cross-iteration safety: `list` is overwritten only after the first
// __syncthreads below, which every thread reaches only after it finished
// consuming `list` from the previous call.
// ---------------------------------------------------------------------------
__device__ __forceinline__ int build_list(const float* __restrict__ row,
                                          uint16_t* list, uint32_t* maskw,
                                          int* basew, int* cntp)
{
    int tid = threadIdx.x, warp = tid >> 5, lane = tid & 31;
    #pragma unroll
    for (int ci = warp; ci < 16; ci += 4) {
        float sv = row[ci * 32 + lane];
        uint32_t m = __ballot_sync(0xffffffffu, sv != 0.f);
        if (lane == 0) maskw[ci] = m;
    }
    __syncthreads();
    if (tid == 0) {
        int s = 0;
        #pragma unroll
        for (int ci = 0; ci < 16; ci++) { basew[ci] = s; s += __popc(maskw[ci]); }
        *cntp = s;
    }
    __syncthreads();
    #pragma unroll
    for (int ci = warp; ci < 16; ci += 4) {
        uint32_t m = maskw[ci];
        if (m & (1u << lane))
            list[basew[ci] + __popc(m & ((1u << lane) - 1u))] = (uint16_t)(ci * 32 + lane);
    }
    __syncthreads();
    return *cntp;
}

// ---------------------------------------------------------------------------
// Fused Q/K/V gather-GEMM + BN + LIF (vth=1).  Block = (b, n); loops t,
// carrying LIF state in registers. Writes SPIKES directly to g_sq/g_sk/g_sv.
// Thread owns d = 4*tid .. 4*tid+3.
// ---------------------------------------------------------------------------
__global__ __launch_bounds__(128)
void gather_qkv_lif_kernel(const float* __restrict__ qg, const float* __restrict__ qb,
                           const float* __restrict__ qm, const float* __restrict__ qv,
                           const float* __restrict__ kg, const float* __restrict__ kb,
                           const float* __restrict__ km, const float* __restrict__ kv,
                           const float* __restrict__ vg, const float* __restrict__ vb,
                           const float* __restrict__ vm, const float* __restrict__ vv)
{
    int b = blockIdx.y, n = blockIdx.x;
    int tid = threadIdx.x;

    __shared__ uint16_t list[C_];
    __shared__ uint32_t maskw[16];
    __shared__ int basew[16];
    __shared__ int cnt;

    const float4* Wq4 = (const float4*)(g_wt + 0 * (size_t)CC);
    const float4* Wk4 = (const float4*)(g_wt + 1 * (size_t)CC);
    const float4* Wv4 = (const float4*)(g_wt + 2 * (size_t)CC);

    // BN constants for this thread's 4 channels, per branch
    float4 qs_c, qs_h, ks_c, ks_h, vs_c, vs_h;
    {
        float4 g = ((const float4*)qg)[tid], bb = ((const float4*)qb)[tid];
        float4 m = ((const float4*)qm)[tid], v = ((const float4*)qv)[tid];
        qs_c.x = g.x * rsqrtf(v.x + EPS_); qs_h.x = bb.x - m.x * qs_c.x;
        qs_c.y = g.y * rsqrtf(v.y + EPS_); qs_h.y = bb.y - m.y * qs_c.y;
        qs_c.z = g.z * rsqrtf(v.z + EPS_); qs_h.z = bb.z - m.z * qs_c.z;
        qs_c.w = g.w * rsqrtf(v.w + EPS_); qs_h.w = bb.w - m.w * qs_c.w;
    }
    {
        float4 g = ((const float4*)kg)[tid], bb = ((const float4*)kb)[tid];
        float4 m = ((const float4*)km)[tid], v = ((const float4*)kv)[tid];
        ks_c.x = g.x * rsqrtf(v.x + EPS_); ks_h.x = bb.x - m.x * ks_c.x;
        ks_c.y = g.y * rsqrtf(v.y + EPS_); ks_h.y = bb.y - m.y * ks_c.y;
        ks_c.z = g.z * rsqrtf(v.z + EPS_); ks_h.z = bb.z - m.z * ks_c.z;
        ks_c.w = g.w * rsqrtf(v.w + EPS_); ks_h.w = bb.w - m.w * ks_c.w;
    }
    {
        float4 g = ((const float4*)vg)[tid], bb = ((const float4*)vb)[tid];
        float4 m = ((const float4*)vm)[tid], v = ((const float4*)vv)[tid];
        vs_c.x = g.x * rsqrtf(v.x + EPS_); vs_h.x = bb.x - m.x * vs_c.x;
        vs_c.y = g.y * rsqrtf(v.y + EPS_); vs_h.y = bb.y - m.y * vs_c.y;
        vs_c.z = g.z * rsqrtf(v.z + EPS_); vs_h.z = bb.z - m.z * vs_c.z;
        vs_c.w = g.w * rsqrtf(v.w + EPS_); vs_h.w = bb.w - m.w * vs_c.w;
    }

    float4 mq = {0.f,0.f,0.f,0.f}, mk = mq, mv = mq;   // LIF membranes

    for (int t = 0; t < T_; t++) {
        int tb = t * B_ + b;
        const float* xrow = g_xs + ((size_t)tb * N_ + n) * C_;
        int count = build_list(xrow, list, maskw, basew, &cnt);

        float4 aq = {0.f,0.f,0.f,0.f}, ak = aq, av = aq;
        for (int i = 0; i < count; i++) {
            int c = list[i];
            float4 wq = Wq4[(size_t)c * 128 + tid];
            float4 wk = Wk4[(size_t)c * 128 + tid];
            float4 wv = Wv4[(size_t)c * 128 + tid];
            aq.x += wq.x; aq.y += wq.y; aq.z += wq.z; aq.w += wq.w;
            ak.x += wk.x; ak.y += wk.y; ak.z += wk.z; ak.w += wk.w;
            av.x += wv.x; av.y += wv.y; av.z += wv.z; av.w += wv.w;
        }

        size_t orow = ((size_t)tb * N_ + n) * C_;
        // q: BN + LIF
        {
            float y0 = aq.x * qs_c.x + qs_h.x, y1 = aq.y * qs_c.y + qs_h.y;
            float y2 = aq.z * qs_c.z + qs_h.z, y3 = aq.w * qs_c.w + qs_h.w;
            float4 o;
            mq.x = fmaf(y0 - mq.x, 0.5f, mq.x); o.x = (mq.x >= 1.f) ? 1.f : 0.f; mq.x = (mq.x >= 1.f) ? 0.f : mq.x;
            mq.y = fmaf(y1 - mq.y, 0.5f, mq.y); o.y = (mq.y >= 1.f) ? 1.f : 0.f; mq.y = (mq.y >= 1.f) ? 0.f : mq.y;
            mq.z = fmaf(y2 - mq.z, 0.5f, mq.z); o.z = (mq.z >= 1.f) ? 1.f : 0.f; mq.z = (mq.z >= 1.f) ? 0.f : mq.z;
            mq.w = fmaf(y3 - mq.w, 0.5f, mq.w); o.w = (mq.w >= 1.f) ? 1.f : 0.f; mq.w = (mq.w >= 1.f) ? 0.f : mq.w;
            ((float4*)(g_sq + orow))[tid] = o;
        }
        // k
        {
            float y0 = ak.x * ks_c.x + ks_h.x, y1 = ak.y * ks_c.y + ks_h.y;
            float y2 = ak.z * ks_c.z + ks_h.z, y3 = ak.w * ks_c.w + ks_h.w;
            float4 o;
            mk.x = fmaf(y0 - mk.x, 0.5f, mk.x); o.x = (mk.x >= 1.f) ? 1.f : 0.f; mk.x = (mk.x >= 1.f) ? 0.f : mk.x;
            mk.y = fmaf(y1 - mk.y, 0.5f, mk.y); o.y = (mk.y >= 1.f) ? 1.f : 0.f; mk.y = (mk.y >= 1.f) ? 0.f : mk.y;
            mk.z = fmaf(y2 - mk.z, 0.5f, mk.z); o.z = (mk.z >= 1.f) ? 1.f : 0.f; mk.z = (mk.z >= 1.f) ? 0.f : mk.z;
            mk.w = fmaf(y3 - mk.w, 0.5f, mk.w); o.w = (mk.w >= 1.f) ? 1.f : 0.f; mk.w = (mk.w >= 1.f) ? 0.f : mk.w;
            ((float4*)(g_sk + orow))[tid] = o;
        }
        // v
        {
            float y0 = av.x * vs_c.x + vs_h.x, y1 = av.y * vs_c.y + vs_h.y;
            float y2 = av.z * vs_c.z + vs_h.z, y3 = av.w * vs_c.w + vs_h.w;
            float4 o;
            mv.x = fmaf(y0 - mv.x, 0.5f, mv.x); o.x = (mv.x >= 1.f) ? 1.f : 0.f; mv.x = (mv.x >= 1.f) ? 0.f : mv.x;
            mv.y = fmaf(y1 - mv.y, 0.5f, mv.y); o.y = (mv.y >= 1.f) ? 1.f : 0.f; mv.y = (mv.y >= 1.f) ? 0.f : mv.y;
            mv.z = fmaf(y2 - mv.z, 0.5f, mv.z); o.z = (mv.z >= 1.f) ? 1.f : 0.f; mv.z = (mv.z >= 1.f) ? 0.f : mv.z;
            mv.w = fmaf(y3 - mv.w, 0.5f, mv.w); o.w = (mv.w >= 1.f) ? 1.f : 0.f; mv.w = (mv.w >= 1.f) ? 0.f : mv.w;
            ((float4*)(g_sv + orow))[tid] = o;
        }
    }
}

// ---------------------------------------------------------------------------
// KV[e][dd] = 0.125 * sum_n k[tb][n][h64+e] * v[tb][n][h64+dd]  per (tb,h)
// (0.125 folded here instead of qkv_apply)
// ---------------------------------------------------------------------------
__global__ __launch_bounds__(256)
void kv_kernel()
{
    int idx = blockIdx.x;                   // tb*8 + h
    int tb = idx >> 3, h = idx & 7;
    const float* Kb = g_sk + (size_t)tb * N_ * C_ + h * HD_;
    const float* Vb = g_sv + (size_t)tb * N_ * C_ + h * HD_;
    float* KVb = g_kv + (size_t)idx * HD_ * HD_;

    __shared__ float Ks[64][65];
    __shared__ float Vs[64][65];

    int tid = threadIdx.x;
    int tx = tid & 15, ty = tid >> 4;
    int le = tid & 63, lr = tid >> 6;
    float acc[4][4];
    #pragma unroll
    for (int i = 0; i < 4; i++)
        #pragma unroll
        for (int j = 0; j < 4; j++) acc[i][j] = 0.f;

    for (int n0 = 0; n0 < N_; n0 += 64) {
        #pragma unroll
        for (int r = 0; r < 16; r++) {
            int nn = lr + 4 * r;
            Ks[le][nn] = Kb[(size_t)(n0 + nn) * C_ + le];
            Vs[le][nn] = Vb[(size_t)(n0 + nn) * C_ + le];
        }
        __syncthreads();
        #pragma unroll 8
        for (int nn = 0; nn < 64; nn++) {
            float a[4], b[4];
            #pragma unroll
            for (int i = 0; i < 4; i++) a[i] = Ks[ty * 4 + i][nn];
            #pragma unroll
            for (int j = 0; j < 4; j++) b[j] = Vs[tx * 4 + j][nn];
            #pragma unroll
            for (int i = 0; i < 4; i++)
                #pragma unroll
                for (int j = 0; j < 4; j++)
                    acc[i][j] = fmaf(a[i], b[j], acc[i][j]);
        }
        __syncthreads();
    }
    #pragma unroll
    for (int i = 0; i < 4; i++)
        #pragma unroll
        for (int j = 0; j < 4; j++)
            KVb[(size_t)(ty * 4 + i) * HD_ + (tx * 4 + j)] = acc[i][j] * 0.125f;
}

// ---------------------------------------------------------------------------
// o_pre[tb][n][h64+dd] = sum_e q[tb][n][h64+e] * KV[e][dd] -> g_y
// (KV already carries the 0.125). q spikes 0/1 -> conditional adds.
// ---------------------------------------------------------------------------
__global__ __launch_bounds__(128)
void qkv_apply_kernel()
{
    int idx = blockIdx.y;                   // tb*8 + h
    int tb = idx >> 3, h = idx & 7;
    int n = blockIdx.x * 128 + threadIdx.x;
    const float* qrow = g_sq + ((size_t)tb * N_ + n) * C_ + h * HD_;
    const float* KVb = g_kv + (size_t)idx * HD_ * HD_;
    float* orow = g_y + ((size_t)tb * N_ + n) * C_ + h * HD_;

    __shared__ __align__(16) float KVs[HD_ * HD_];
    for (int i = threadIdx.x; i < HD_ * HD_; i += 128) KVs[i] = KVb[i];
    __syncthreads();

    float acc[64];
    #pragma unroll
    for (int d = 0; d < 64; d++) acc[d] = 0.f;

    #pragma unroll 4
    for (int e4 = 0; e4 < 16; e4++) {
        float4 q4 = ((const float4*)qrow)[e4];
        float qs[4] = {q4.x, q4.y, q4.z, q4.w};
        #pragma unroll
        for (int s = 0; s < 4; s++) {
            if (qs[s] != 0.f) {
                const float4* row = (const float4*)(KVs + (e4 * 4 + s) * 64);
                #pragma unroll
                for (int dq = 0; dq < 16; dq++) {
                    float4 kvv = row[dq];
                    acc[dq * 4 + 0] += kvv.x;
                    acc[dq * 4 + 1] += kvv.y;
                    acc[dq * 4 + 2] += kvv.z;
                    acc[dq * 4 + 3] += kvv.w;
                }
            }
        }
    }
    #pragma unroll
    for (int q = 0; q < 16; q++) {
        float4 o = {acc[q*4+0], acc[q*4+1], acc[q*4+2], acc[q*4+3]};
        ((float4*)orow)[q] = o;
    }
}

// ---------------------------------------------------------------------------
// Fused attn-LIF (vth=0.5) + projection gather-GEMM + bias + BN.
// Block = (b, n), loops t with LIF state in registers; spikes staged in smem
// for the list build. Writes [tb][n][c] COALESCED into g_ot.
// ---------------------------------------------------------------------------
__global__ __launch_bounds__(128)
void gather_proj_lif_kernel(const float* __restrict__ bp,
                            const float* __restrict__ pg, const float* __restrict__ pb,
                            const float* __restrict__ pm, const float* __restrict__ pv)
{
    int b = blockIdx.y, n = blockIdx.x;
    int tid = threadIdx.x;

    __shared__ float srow[C_];
    __shared__ uint16_t list[C_];
    __shared__ uint32_t maskw[16];
    __shared__ int basew[16];
    __shared__ int cnt;

    const float4* Wp4 = (const float4*)(g_wt + 3 * (size_t)CC);

    // folded bias+BN constants for this thread's 4 channels
    float4 sc, sh;
    {
        float4 g = ((const float4*)pg)[tid], bb = ((const float4*)pb)[tid];
        float4 m = ((const float4*)pm)[tid], v = ((const float4*)pv)[tid];
        float4 bi = ((const float4*)bp)[tid];
        sc.x = g.x * rsqrtf(v.x + EPS_); sh.x = bb.x + (bi.x - m.x) * sc.x;
        sc.y = g.y * rsqrtf(v.y + EPS_); sh.y = bb.y + (bi.y - m.y) * sc.y;
        sc.z = g.z * rsqrtf(v.z + EPS_); sh.z = bb.z + (bi.z - m.z) * sc.z;
        sc.w = g.w * rsqrtf(v.w + EPS_); sh.w = bb.w + (bi.w - m.w) * sc.w;
    }

    float4 mo = {0.f, 0.f, 0.f, 0.f};    // attn-LIF membrane

    for (int t = 0; t < T_; t++) {
        int tb = t * B_ + b;
        // attn LIF on this thread's 4 channels
        float4 y = ((const float4*)(g_y + ((size_t)tb * N_ + n) * C_))[tid];
        float4 s4;
        mo.x = fmaf(y.x - mo.x, 0.5f, mo.x); s4.x = (mo.x >= 0.5f) ? 1.f : 0.f; mo.x = (mo.x >= 0.5f) ? 0.f : mo.x;
        mo.y = fmaf(y.y - mo.y, 0.5f, mo.y); s4.y = (mo.y >= 0.5f) ? 1.f : 0.f; mo.y = (mo.y >= 0.5f) ? 0.f : mo.y;
        mo.z = fmaf(y.z - mo.z, 0.5f, mo.z); s4.z = (mo.z >= 0.5f) ? 1.f : 0.f; mo.z = (mo.z >= 0.5f) ? 0.f : mo.z;
        mo.w = fmaf(y.w - mo.w, 0.5f, mo.w); s4.w = (mo.w >= 0.5f) ? 1.f : 0.f; mo.w = (mo.w >= 0.5f) ? 0.f : mo.w;
        ((float4*)srow)[tid] = s4;
        __syncthreads();

        int count = build_list(srow, list, maskw, basew, &cnt);

        float4 ap = {0.f, 0.f, 0.f, 0.f};
        for (int i = 0; i < count; i++) {
            int c = list[i];
            float4 wp = Wp4[(size_t)c * 128 + tid];
            ap.x += wp.x; ap.y += wp.y; ap.z += wp.z; ap.w += wp.w;
        }

        float4 o;
        o.x = ap.x * sc.x + sh.x;
        o.y = ap.y * sc.y + sh.y;
        o.z = ap.z * sc.z + sh.z;
        o.w = ap.w * sc.w + sh.w;
        ((float4*)(g_ot + ((size_t)tb * N_ + n) * C_))[tid] = o;
        __syncthreads();   // protect srow before next t overwrites it
    }
}

// ---------------------------------------------------------------------------
// Final transpose: g_ot [tb][n][c] -> out [tb][c][n] (both sides coalesced)
// ---------------------------------------------------------------------------
__global__ __launch_bounds__(256)
void transpose_out_kernel(float* __restrict__ out)
{
    int tb = blockIdx.z;
    int n0 = blockIdx.y * 32;
    int c0 = blockIdx.x * 32;
    int tx = threadIdx.x & 31, ty = threadIdx.x >> 5;
    __shared__ float s[32][33];
    const float* src = g_ot + (size_t)tb * N_ * C_;
    float* dst = out + (size_t)tb * C_ * N_;
    #pragma unroll
    for (int r = 0; r < 4; r++)
        s[ty + 8 * r][tx] = src[(size_t)(n0 + ty + 8 * r) * C_ + c0 + tx];
    __syncthreads();
    #pragma unroll
    for (int r = 0; r < 4; r++)
        dst[(size_t)(c0 + ty + 8 * r) * N_ + n0 + tx] = s[tx][ty + 8 * r];
}

// ---------------------------------------------------------------------------
// Launch
// ---------------------------------------------------------------------------
extern "C" void kernel_launch(void* const* d_in, const int* in_sizes, int n_in,
                              void* d_out, int out_size)
{
    const float* x   = (const float*)d_in[0];
    const float* Wq  = (const float*)d_in[1];
    const float* q_g = (const float*)d_in[2];
    const float* q_b = (const float*)d_in[3];
    const float* q_m = (const float*)d_in[4];
    const float* q_v = (const float*)d_in[5];
    const float* Wk  = (const float*)d_in[6];
    const float* k_g = (const float*)d_in[7];
    const float* k_b = (const float*)d_in[8];
    const float* k_m = (const float*)d_in[9];
    const float* k_v = (const float*)d_in[10];
    const float* Wv  = (const float*)d_in[11];
    const float* v_g = (const float*)d_in[12];
    const float* v_b = (const float*)d_in[13];
    const float* v_m = (const float*)d_in[14];
    const float* v_v = (const float*)d_in[15];
    const float* Wp  = (const float*)d_in[16];
    const float* bp  = (const float*)d_in[17];
    const float* p_g = (const float*)d_in[18];
    const float* p_b = (const float*)d_in[19];
    const float* p_m = (const float*)d_in[20];
    const float* p_v = (const float*)d_in[21];
    float* out = (float*)d_out;

    // 0: weight transposes (all branches, one launch)
    prep_wt_kernel<<<dim3(C_ / 32, C_ / 32, 4), 256>>>(Wq, Wk, Wv, Wp);

    // 1: input LIF -> [tb][n][c] spikes
    lif_in_transpose_kernel<<<dim3(N_ / 32, C_ / 32, B_), 256>>>(x);

    // 2: fused QKV gather + BN + LIF -> spike buffers
    gather_qkv_lif_kernel<<<dim3(N_, B_), 128>>>(
        q_g, q_b, q_m, q_v, k_g, k_b, k_m, k_v, v_g, v_b, v_m, v_v);

    // 3-4: attention (exact re-association)
    kv_kernel<<<TBAT * NH_, 256>>>();
    qkv_apply_kernel<<<dim3(N_ / 128, TBAT * NH_), 128>>>();

    // 5: fused attn-LIF + projection gather + bias + BN -> g_ot [tb][n][c]
    gather_proj_lif_kernel<<<dim3(N_, B_), 128>>>(bp, p_g, p_b, p_m, p_v);

    // 6: transpose to final layout [tb][c][n]
    transpose_out_kernel<<<dim3(C_ / 32, N_ / 32, TBAT), 256>>>(out);
}

// round 10
// speedup vs baseline: 18.0897x; 1.2962x over previous
#include <cuda_runtime.h>
#include <cstdint>

// ---------------------------------------------------------------------------
// Problem constants
// ---------------------------------------------------------------------------
#define T_  4
#define B_  4
#define C_  512
#define N_  1024          // H*W
#define NH_ 8
#define HD_ 64
#define TBAT (T_*B_)
#define BCN  (B_*C_*N_)   // 2,097,152
#define CC   (C_*C_)
#define EPS_ 1e-5f

// ---------------------------------------------------------------------------
// Device scratch (static — no allocation anywhere)
// Activations in [tb][n][c] layout (c contiguous) unless noted.
// ---------------------------------------------------------------------------
__device__ float g_wt[4 * CC];        // W^T per branch: [w][c][d]
__device__ float g_xs[T_ * BCN];      // input spikes   [tb][n][c]
__device__ float g_sq[T_ * BCN];      // q spikes       [tb][n][c]
__device__ float g_sk[T_ * BCN];
__device__ float g_sv[T_ * BCN];
__device__ float g_y [T_ * BCN];      // o_pre scratch  [tb][n][c]
__device__ float g_ot[T_ * BCN];      // proj output    [tb][n][c] (pre-transpose)
__device__ float g_kv[TBAT * NH_ * HD_ * HD_];   // [tb*8+h][e][dd]
__device__ uint32_t g_mk[TBAT * C_ * 32];        // k spike bitmasks [tb][c][nword]
__device__ uint32_t g_mv[TBAT * C_ * 32];        // v spike bitmasks

// ---------------------------------------------------------------------------
// Weight transpose (all 4 branches, one launch): W[d][c] -> g_wt[w][c][d]
// ---------------------------------------------------------------------------
__global__ __launch_bounds__(256)
void prep_wt_kernel(const float* __restrict__ Wq, const float* __restrict__ Wk,
                    const float* __restrict__ Wv, const float* __restrict__ Wp)
{
    int w = blockIdx.z;
    const float* src = (w == 0) ? Wq : (w == 1) ? Wk : (w == 2) ? Wv : Wp;
    float* dst = g_wt + (size_t)w * CC;
    int d0 = blockIdx.y * 32, c0 = blockIdx.x * 32;
    int tx = threadIdx.x & 31, ty = threadIdx.x >> 5;
    __shared__ float s[32][33];
    #pragma unroll
    for (int r = 0; r < 4; r++)
        s[ty + 8 * r][tx] = src[(size_t)(d0 + ty + 8 * r) * C_ + c0 + tx];
    __syncthreads();
    #pragma unroll
    for (int r = 0; r < 4; r++)
        dst[(size_t)(c0 + ty + 8 * r) * C_ + d0 + tx] = s[tx][ty + 8 * r];
}

// ---------------------------------------------------------------------------
// Input LIF with transpose: x fp32 [t,b,c,n] -> g_xs fp32 [t,b,n,c], vth=1
// ---------------------------------------------------------------------------
__global__ __launch_bounds__(256)
void lif_in_transpose_kernel(const float* __restrict__ x)
{
    int b  = blockIdx.z;
    int c0 = blockIdx.y * 32;
    int n0 = blockIdx.x * 32;
    int tx = threadIdx.x & 31, ty = threadIdx.x >> 5;
    __shared__ float s[32][33];
    float v[4] = {0.f, 0.f, 0.f, 0.f};

    for (int t = 0; t < T_; t++) {
        #pragma unroll
        for (int r = 0; r < 4; r++) {
            int c = c0 + ty + 8 * r;
            float xv = x[(((size_t)t * B_ + b) * C_ + c) * (size_t)N_ + n0 + tx];
            float vv = v[r];
            vv = fmaf(xv - vv, 0.5f, vv);
            float sp = (vv >= 1.0f) ? 1.f : 0.f;
            v[r] = (vv >= 1.0f) ? 0.f : vv;
            s[ty + 8 * r][tx] = sp;
        }
        __syncthreads();
        #pragma unroll
        for (int r = 0; r < 4; r++) {
            int n = n0 + ty + 8 * r;
            g_xs[(((size_t)t * B_ + b) * N_ + n) * C_ + c0 + tx] = s[tx][ty + 8 * r];
        }
        __syncthreads();
    }
}

// ---------------------------------------------------------------------------
// Deterministic active-channel list build (ballot + popc prefix, ascending c)
// ---------------------------------------------------------------------------
__device__ __forceinline__ int build_list(const float* __restrict__ row,
                                          uint16_t* list, uint32_t* maskw,
                                          int* basew, int* cntp)
{
    int tid = threadIdx.x, warp = tid >> 5, lane = tid & 31;
    #pragma unroll
    for (int ci = warp; ci < 16; ci += 4) {
        float sv = row[ci * 32 + lane];
        uint32_t m = __ballot_sync(0xffffffffu, sv != 0.f);
        if (lane == 0) maskw[ci] = m;
    }
    __syncthreads();
    if (tid == 0) {
        int s = 0;
        #pragma unroll
        for (int ci = 0; ci < 16; ci++) { basew[ci] = s; s += __popc(maskw[ci]); }
        *cntp = s;
    }
    __syncthreads();
    #pragma unroll
    for (int ci = warp; ci < 16; ci += 4) {
        uint32_t m = maskw[ci];
        if (m & (1u << lane))
            list[basew[ci] + __popc(m & ((1u << lane) - 1u))] = (uint16_t)(ci * 32 + lane);
    }
    __syncthreads();
    return *cntp;
}

// ---------------------------------------------------------------------------
// Fused Q/K/V gather-GEMM + BN + LIF (vth=1).  Block = (b, n); loops t.
// ---------------------------------------------------------------------------
__global__ __launch_bounds__(128)
void gather_qkv_lif_kernel(const float* __restrict__ qg, const float* __restrict__ qb,
                           const float* __restrict__ qm, const float* __restrict__ qv,
                           const float* __restrict__ kg, const float* __restrict__ kb,
                           const float* __restrict__ km, const float* __restrict__ kv,
                           const float* __restrict__ vg, const float* __restrict__ vb,
                           const float* __restrict__ vm, const float* __restrict__ vv)
{
    int b = blockIdx.y, n = blockIdx.x;
    int tid = threadIdx.x;

    __shared__ uint16_t list[C_];
    __shared__ uint32_t maskw[16];
    __shared__ int basew[16];
    __shared__ int cnt;

    const float4* Wq4 = (const float4*)(g_wt + 0 * (size_t)CC);
    const float4* Wk4 = (const float4*)(g_wt + 1 * (size_t)CC);
    const float4* Wv4 = (const float4*)(g_wt + 2 * (size_t)CC);

    float4 qs_c, qs_h, ks_c, ks_h, vs_c, vs_h;
    {
        float4 g = ((const float4*)qg)[tid], bb = ((const float4*)qb)[tid];
        float4 m = ((const float4*)qm)[tid], v = ((const float4*)qv)[tid];
        qs_c.x = g.x * rsqrtf(v.x + EPS_); qs_h.x = bb.x - m.x * qs_c.x;
        qs_c.y = g.y * rsqrtf(v.y + EPS_); qs_h.y = bb.y - m.y * qs_c.y;
        qs_c.z = g.z * rsqrtf(v.z + EPS_); qs_h.z = bb.z - m.z * qs_c.z;
        qs_c.w = g.w * rsqrtf(v.w + EPS_); qs_h.w = bb.w - m.w * qs_c.w;
    }
    {
        float4 g = ((const float4*)kg)[tid], bb = ((const float4*)kb)[tid];
        float4 m = ((const float4*)km)[tid], v = ((const float4*)kv)[tid];
        ks_c.x = g.x * rsqrtf(v.x + EPS_); ks_h.x = bb.x - m.x * ks_c.x;
        ks_c.y = g.y * rsqrtf(v.y + EPS_); ks_h.y = bb.y - m.y * ks_c.y;
        ks_c.z = g.z * rsqrtf(v.z + EPS_); ks_h.z = bb.z - m.z * ks_c.z;
        ks_c.w = g.w * rsqrtf(v.w + EPS_); ks_h.w = bb.w - m.w * ks_c.w;
    }
    {
        float4 g = ((const float4*)vg)[tid], bb = ((const float4*)vb)[tid];
        float4 m = ((const float4*)vm)[tid], v = ((const float4*)vv)[tid];
        vs_c.x = g.x * rsqrtf(v.x + EPS_); vs_h.x = bb.x - m.x * vs_c.x;
        vs_c.y = g.y * rsqrtf(v.y + EPS_); vs_h.y = bb.y - m.y * vs_c.y;
        vs_c.z = g.z * rsqrtf(v.z + EPS_); vs_h.z = bb.z - m.z * vs_c.z;
        vs_c.w = g.w * rsqrtf(v.w + EPS_); vs_h.w = bb.w - m.w * vs_c.w;
    }

    float4 mq = {0.f,0.f,0.f,0.f}, mk = mq, mv = mq;

    for (int t = 0; t < T_; t++) {
        int tb = t * B_ + b;
        const float* xrow = g_xs + ((size_t)tb * N_ + n) * C_;
        int count = build_list(xrow, list, maskw, basew, &cnt);

        float4 aq = {0.f,0.f,0.f,0.f}, ak = aq, av = aq;
        for (int i = 0; i < count; i++) {
            int c = list[i];
            float4 wq = Wq4[(size_t)c * 128 + tid];
            float4 wk = Wk4[(size_t)c * 128 + tid];
            float4 wv = Wv4[(size_t)c * 128 + tid];
            aq.x += wq.x; aq.y += wq.y; aq.z += wq.z; aq.w += wq.w;
            ak.x += wk.x; ak.y += wk.y; ak.z += wk.z; ak.w += wk.w;
            av.x += wv.x; av.y += wv.y; av.z += wv.z; av.w += wv.w;
        }

        size_t orow = ((size_t)tb * N_ + n) * C_;
        {
            float y0 = aq.x * qs_c.x + qs_h.x, y1 = aq.y * qs_c.y + qs_h.y;
            float y2 = aq.z * qs_c.z + qs_h.z, y3 = aq.w * qs_c.w + qs_h.w;
            float4 o;
            mq.x = fmaf(y0 - mq.x, 0.5f, mq.x); o.x = (mq.x >= 1.f) ? 1.f : 0.f; mq.x = (mq.x >= 1.f) ? 0.f : mq.x;
            mq.y = fmaf(y1 - mq.y, 0.5f, mq.y); o.y = (mq.y >= 1.f) ? 1.f : 0.f; mq.y = (mq.y >= 1.f) ? 0.f : mq.y;
            mq.z = fmaf(y2 - mq.z, 0.5f, mq.z); o.z = (mq.z >= 1.f) ? 1.f : 0.f; mq.z = (mq.z >= 1.f) ? 0.f : mq.z;
            mq.w = fmaf(y3 - mq.w, 0.5f, mq.w); o.w = (mq.w >= 1.f) ? 1.f : 0.f; mq.w = (mq.w >= 1.f) ? 0.f : mq.w;
            ((float4*)(g_sq + orow))[tid] = o;
        }
        {
            float y0 = ak.x * ks_c.x + ks_h.x, y1 = ak.y * ks_c.y + ks_h.y;
            float y2 = ak.z * ks_c.z + ks_h.z, y3 = ak.w * ks_c.w + ks_h.w;
            float4 o;
            mk.x = fmaf(y0 - mk.x, 0.5f, mk.x); o.x = (mk.x >= 1.f) ? 1.f : 0.f; mk.x = (mk.x >= 1.f) ? 0.f : mk.x;
            mk.y = fmaf(y1 - mk.y, 0.5f, mk.y); o.y = (mk.y >= 1.f) ? 1.f : 0.f; mk.y = (mk.y >= 1.f) ? 0.f : mk.y;
            mk.z = fmaf(y2 - mk.z, 0.5f, mk.z); o.z = (mk.z >= 1.f) ? 1.f : 0.f; mk.z = (mk.z >= 1.f) ? 0.f : mk.z;
            mk.w = fmaf(y3 - mk.w, 0.5f, mk.w); o.w = (mk.w >= 1.f) ? 1.f : 0.f; mk.w = (mk.w >= 1.f) ? 0.f : mk.w;
            ((float4*)(g_sk + orow))[tid] = o;
        }
        {
            float y0 = av.x * vs_c.x + vs_h.x, y1 = av.y * vs_c.y + vs_h.y;
            float y2 = av.z * vs_c.z + vs_h.z, y3 = av.w * vs_c.w + vs_h.w;
            float4 o;
            mv.x = fmaf(y0 - mv.x, 0.5f, mv.x); o.x = (mv.x >= 1.f) ? 1.f : 0.f; mv.x = (mv.x >= 1.f) ? 0.f : mv.x;
            mv.y = fmaf(y1 - mv.y, 0.5f, mv.y); o.y = (mv.y >= 1.f) ? 1.f : 0.f; mv.y = (mv.y >= 1.f) ? 0.f : mv.y;
            mv.z = fmaf(y2 - mv.z, 0.5f, mv.z); o.z = (mv.z >= 1.f) ? 1.f : 0.f; mv.z = (mv.z >= 1.f) ? 0.f : mv.z;
            mv.w = fmaf(y3 - mv.w, 0.5f, mv.w); o.w = (mv.w >= 1.f) ? 1.f : 0.f; mv.w = (mv.w >= 1.f) ? 0.f : mv.w;
            ((float4*)(g_sv + orow))[tid] = o;
        }
    }
}

// ---------------------------------------------------------------------------
// Pack k/v spikes into bitmasks over n: g_mk/g_mv [tb][c][nword]
// Block = (nword, tb), 512 threads = all c. Reads coalesced across c.
// ---------------------------------------------------------------------------
__global__ __launch_bounds__(512)
void spike_mask_kernel()
{
    int nw = blockIdx.x, tb = blockIdx.y;
    int c = threadIdx.x;
    const float* K = g_sk + ((size_t)tb * N_ + nw * 32) * C_ + c;
    const float* V = g_sv + ((size_t)tb * N_ + nw * 32) * C_ + c;
    uint32_t wk = 0, wv = 0;
    #pragma unroll
    for (int i = 0; i < 32; i++) {
        wk |= (uint32_t)(K[(size_t)i * C_] != 0.f) << i;
        wv |= (uint32_t)(V[(size_t)i * C_] != 0.f) << i;
    }
    g_mk[((size_t)tb * C_ + c) * 32 + nw] = wk;
    g_mv[((size_t)tb * C_ + c) * 32 + nw] = wv;
}

// ---------------------------------------------------------------------------
// KV[e][dd] = 0.125 * popc-sum(maskK_e & maskV_dd)  per (tb,h) — exact.
// ---------------------------------------------------------------------------
__global__ __launch_bounds__(256)
void kv_popc_kernel()
{
    int idx = blockIdx.x;                   // tb*8 + h
    int tb = idx >> 3, h = idx & 7;
    float* KVb = g_kv + (size_t)idx * HD_ * HD_;

    __shared__ uint32_t MK[64][32];
    __shared__ uint32_t MV[64][32];

    int tid = threadIdx.x;
    for (int i = tid; i < 64 * 32; i += 256) {
        int e = i >> 5, w = i & 31;
        MK[e][w] = g_mk[((size_t)tb * C_ + h * HD_ + e) * 32 + w];
        MV[e][w] = g_mv[((size_t)tb * C_ + h * HD_ + e) * 32 + w];
    }
    __syncthreads();

    #pragma unroll
    for (int r = 0; r < 16; r++) {
        int p = r * 256 + tid;              // 0..4095
        int e = p >> 6, dd = p & 63;
        int s = 0;
        #pragma unroll
        for (int w = 0; w < 32; w++)
            s += __popc(MK[e][w] & MV[dd][w]);
        KVb[(size_t)e * HD_ + dd] = (float)s * 0.125f;
    }
}

// ---------------------------------------------------------------------------
// o_pre[tb][n][h64+dd] = sum_e q[tb][n][h64+e] * KV[e][dd] -> g_y
// ---------------------------------------------------------------------------
__global__ __launch_bounds__(128)
void qkv_apply_kernel()
{
    int idx = blockIdx.y;                   // tb*8 + h
    int tb = idx >> 3, h = idx & 7;
    int n = blockIdx.x * 128 + threadIdx.x;
    const float* qrow = g_sq + ((size_t)tb * N_ + n) * C_ + h * HD_;
    const float* KVb = g_kv + (size_t)idx * HD_ * HD_;
    float* orow = g_y + ((size_t)tb * N_ + n) * C_ + h * HD_;

    __shared__ __align__(16) float KVs[HD_ * HD_];
    for (int i = threadIdx.x; i < HD_ * HD_; i += 128) KVs[i] = KVb[i];
    __syncthreads();

    float acc[64];
    #pragma unroll
    for (int d = 0; d < 64; d++) acc[d] = 0.f;

    #pragma unroll 4
    for (int e4 = 0; e4 < 16; e4++) {
        float4 q4 = ((const float4*)qrow)[e4];
        float qs[4] = {q4.x, q4.y, q4.z, q4.w};
        #pragma unroll
        for (int s = 0; s < 4; s++) {
            if (qs[s] != 0.f) {
                const float4* row = (const float4*)(KVs + (e4 * 4 + s) * 64);
                #pragma unroll
                for (int dq = 0; dq < 16; dq++) {
                    float4 kvv = row[dq];
                    acc[dq * 4 + 0] += kvv.x;
                    acc[dq * 4 + 1] += kvv.y;
                    acc[dq * 4 + 2] += kvv.z;
                    acc[dq * 4 + 3] += kvv.w;
                }
            }
        }
    }
    #pragma unroll
    for (int q = 0; q < 16; q++) {
        float4 o = {acc[q*4+0], acc[q*4+1], acc[q*4+2], acc[q*4+3]};
        ((float4*)orow)[q] = o;
    }
}

// ---------------------------------------------------------------------------
// Fused attn-LIF (vth=0.5) + projection gather + bias + BN -> g_ot [tb][n][c]
// ---------------------------------------------------------------------------
__global__ __launch_bounds__(128)
void gather_proj_lif_kernel(const float* __restrict__ bp,
                            const float* __restrict__ pg, const float* __restrict__ pb,
                            const float* __restrict__ pm, const float* __restrict__ pv)
{
    int b = blockIdx.y, n = blockIdx.x;
    int tid = threadIdx.x;

    __shared__ float srow[C_];
    __shared__ uint16_t list[C_];
    __shared__ uint32_t maskw[16];
    __shared__ int basew[16];
    __shared__ int cnt;

    const float4* Wp4 = (const float4*)(g_wt + 3 * (size_t)CC);

    float4 sc, sh;
    {
        float4 g = ((const float4*)pg)[tid], bb = ((const float4*)pb)[tid];
        float4 m = ((const float4*)pm)[tid], v = ((const float4*)pv)[tid];
        float4 bi = ((const float4*)bp)[tid];
        sc.x = g.x * rsqrtf(v.x + EPS_); sh.x = bb.x + (bi.x - m.x) * sc.x;
        sc.y = g.y * rsqrtf(v.y + EPS_); sh.y = bb.y + (bi.y - m.y) * sc.y;
        sc.z = g.z * rsqrtf(v.z + EPS_); sh.z = bb.z + (bi.z - m.z) * sc.z;
        sc.w = g.w * rsqrtf(v.w + EPS_); sh.w = bb.w + (bi.w - m.w) * sc.w;
    }

    float4 mo = {0.f, 0.f, 0.f, 0.f};

    for (int t = 0; t < T_; t++) {
        int tb = t * B_ + b;
        float4 y = ((const float4*)(g_y + ((size_t)tb * N_ + n) * C_))[tid];
        float4 s4;
        mo.x = fmaf(y.x - mo.x, 0.5f, mo.x); s4.x = (mo.x >= 0.5f) ? 1.f : 0.f; mo.x = (mo.x >= 0.5f) ? 0.f : mo.x;
        mo.y = fmaf(y.y - mo.y, 0.5f, mo.y); s4.y = (mo.y >= 0.5f) ? 1.f : 0.f; mo.y = (mo.y >= 0.5f) ? 0.f : mo.y;
        mo.z = fmaf(y.z - mo.z, 0.5f, mo.z); s4.z = (mo.z >= 0.5f) ? 1.f : 0.f; mo.z = (mo.z >= 0.5f) ? 0.f : mo.z;
        mo.w = fmaf(y.w - mo.w, 0.5f, mo.w); s4.w = (mo.w >= 0.5f) ? 1.f : 0.f; mo.w = (mo.w >= 0.5f) ? 0.f : mo.w;
        ((float4*)srow)[tid] = s4;
        __syncthreads();

        int count = build_list(srow, list, maskw, basew, &cnt);

        float4 ap = {0.f, 0.f, 0.f, 0.f};
        for (int i = 0; i < count; i++) {
            int c = list[i];
            float4 wp = Wp4[(size_t)c * 128 + tid];
            ap.x += wp.x; ap.y += wp.y; ap.z += wp.z; ap.w += wp.w;
        }

        float4 o;
        o.x = ap.x * sc.x + sh.x;
        o.y = ap.y * sc.y + sh.y;
        o.z = ap.z * sc.z + sh.z;
        o.w = ap.w * sc.w + sh.w;
        ((float4*)(g_ot + ((size_t)tb * N_ + n) * C_))[tid] = o;
        __syncthreads();
    }
}

// ---------------------------------------------------------------------------
// Final transpose: g_ot [tb][n][c] -> out [tb][c][n]
// ---------------------------------------------------------------------------
__global__ __launch_bounds__(256)
void transpose_out_kernel(float* __restrict__ out)
{
    int tb = blockIdx.z;
    int n0 = blockIdx.y * 32;
    int c0 = blockIdx.x * 32;
    int tx = threadIdx.x & 31, ty = threadIdx.x >> 5;
    __shared__ float s[32][33];
    const float* src = g_ot + (size_t)tb * N_ * C_;
    float* dst = out + (size_t)tb * C_ * N_;
    #pragma unroll
    for (int r = 0; r < 4; r++)
        s[ty + 8 * r][tx] = src[(size_t)(n0 + ty + 8 * r) * C_ + c0 + tx];
    __syncthreads();
    #pragma unroll
    for (int r = 0; r < 4; r++)
        dst[(size_t)(c0 + ty + 8 * r) * N_ + n0 + tx] = s[tx][ty + 8 * r];
}

// ---------------------------------------------------------------------------
// Launch
// ---------------------------------------------------------------------------
extern "C" void kernel_launch(void* const* d_in, const int* in_sizes, int n_in,
                              void* d_out, int out_size)
{
    const float* x   = (const float*)d_in[0];
    const float* Wq  = (const float*)d_in[1];
    const float* q_g = (const float*)d_in[2];
    const float* q_b = (const float*)d_in[3];
    const float* q_m = (const float*)d_in[4];
    const float* q_v = (const float*)d_in[5];
    const float* Wk  = (const float*)d_in[6];
    const float* k_g = (const float*)d_in[7];
    const float* k_b = (const float*)d_in[8];
    const float* k_m = (const float*)d_in[9];
    const float* k_v = (const float*)d_in[10];
    const float* Wv  = (const float*)d_in[11];
    const float* v_g = (const float*)d_in[12];
    const float* v_b = (const float*)d_in[13];
    const float* v_m = (const float*)d_in[14];
    const float* v_v = (const float*)d_in[15];
    const float* Wp  = (const float*)d_in[16];
    const float* bp  = (const float*)d_in[17];
    const float* p_g = (const float*)d_in[18];
    const float* p_b = (const float*)d_in[19];
    const float* p_m = (const float*)d_in[20];
    const float* p_v = (const float*)d_in[21];
    float* out = (float*)d_out;

    prep_wt_kernel<<<dim3(C_ / 32, C_ / 32, 4), 256>>>(Wq, Wk, Wv, Wp);
    lif_in_transpose_kernel<<<dim3(N_ / 32, C_ / 32, B_), 256>>>(x);
    gather_qkv_lif_kernel<<<dim3(N_, B_), 128>>>(
        q_g, q_b, q_m, q_v, k_g, k_b, k_m, k_v, v_g, v_b, v_m, v_v);
    spike_mask_kernel<<<dim3(32, TBAT), 512>>>();
    kv_popc_kernel<<<TBAT * NH_, 256>>>();
    qkv_apply_kernel<<<dim3(N_ / 128, TBAT * NH_), 128>>>();
    gather_proj_lif_kernel<<<dim3(N_, B_), 128>>>(bp, p_g, p_b, p_m, p_v);
    transpose_out_kernel<<<dim3(C_ / 32, N_ / 32, TBAT), 256>>>(out);
}

// round 11
// speedup vs baseline: 21.2391x; 1.1741x over previous
#include <cuda_runtime.h>
#include <cstdint>

// ---------------------------------------------------------------------------
// Problem constants
// ---------------------------------------------------------------------------
#define T_  4
#define B_  4
#define C_  512
#define N_  1024          // H*W
#define NH_ 8
#define HD_ 64
#define TBAT (T_*B_)
#define BCN  (B_*C_*N_)   // 2,097,152
#define CC   (C_*C_)
#define EPS_ 1e-5f
#define FULLW 0xffffffffu

// ---------------------------------------------------------------------------
// Device scratch (static — no allocation anywhere)
// Spikes live as bitmasks: row layout [tb][n][16 c-words] (bit = c&31).
// ---------------------------------------------------------------------------
__device__ float    g_wt[4 * CC];          // W^T per branch: [w][c][d]
__device__ uint32_t g_bx[TBAT * N_ * 16];  // input spike bits
__device__ uint32_t g_bq[TBAT * N_ * 16];  // q spike bits
__device__ uint32_t g_bk[TBAT * N_ * 16];  // k spike bits
__device__ uint32_t g_bv[TBAT * N_ * 16];  // v spike bits
__device__ uint32_t g_mk[TBAT * C_ * 32];  // k bits reoriented: [tb][c][32 n-words]
__device__ uint32_t g_mv[TBAT * C_ * 32];
__device__ float    g_y [T_ * BCN];        // o_pre scratch  [tb][n][c]
__device__ float    g_ot[T_ * BCN];        // proj output    [tb][n][c]
__device__ float    g_kv[TBAT * NH_ * HD_ * HD_];  // [tb*8+h][e][dd]

// ---------------------------------------------------------------------------
// Weight transpose (all 4 branches): W[d][c] -> g_wt[w][c][d]
// ---------------------------------------------------------------------------
__global__ __launch_bounds__(256)
void prep_wt_kernel(const float* __restrict__ Wq, const float* __restrict__ Wk,
                    const float* __restrict__ Wv, const float* __restrict__ Wp)
{
    int w = blockIdx.z;
    const float* src = (w == 0) ? Wq : (w == 1) ? Wk : (w == 2) ? Wv : Wp;
    float* dst = g_wt + (size_t)w * CC;
    int d0 = blockIdx.y * 32, c0 = blockIdx.x * 32;
    int tx = threadIdx.x & 31, ty = threadIdx.x >> 5;
    __shared__ float s[32][33];
    #pragma unroll
    for (int r = 0; r < 4; r++)
        s[ty + 8 * r][tx] = src[(size_t)(d0 + ty + 8 * r) * C_ + c0 + tx];
    __syncthreads();
    #pragma unroll
    for (int r = 0; r < 4; r++)
        dst[(size_t)(c0 + ty + 8 * r) * C_ + d0 + tx] = s[tx][ty + 8 * r];
}

// ---------------------------------------------------------------------------
// Input LIF -> spike BITS.  x fp32 [t,b,c,n] -> g_bx[tb][n][c-word], vth=1.
// Block tile: (b, 32c x 32n). Spikes staged in smem, ballot over c.
// ---------------------------------------------------------------------------
__global__ __launch_bounds__(256)
void lif_in_bits_kernel(const float* __restrict__ x)
{
    int b  = blockIdx.z;
    int c0 = blockIdx.y * 32;
    int n0 = blockIdx.x * 32;
    int tx = threadIdx.x & 31, ty = threadIdx.x >> 5;
    int warp = threadIdx.x >> 5, lane = threadIdx.x & 31;
    __shared__ float s[32][33];
    float v[4] = {0.f, 0.f, 0.f, 0.f};

    for (int t = 0; t < T_; t++) {
        #pragma unroll
        for (int r = 0; r < 4; r++) {
            int c = c0 + ty + 8 * r;
            float xv = x[(((size_t)t * B_ + b) * C_ + c) * (size_t)N_ + n0 + tx];
            float vv = v[r];
            vv = fmaf(xv - vv, 0.5f, vv);
            float sp = (vv >= 1.0f) ? 1.f : 0.f;
            v[r] = (vv >= 1.0f) ? 0.f : vv;
            s[ty + 8 * r][tx] = sp;
        }
        __syncthreads();
        // warp w covers n_local 4w..4w+3; ballot over lane = c_local
        int tb = t * B_ + b;
        #pragma unroll
        for (int r = 0; r < 4; r++) {
            int nl = warp * 4 + r;
            uint32_t word = __ballot_sync(FULLW, s[lane][nl] != 0.f);
            if (lane == 0)
                g_bx[((size_t)tb * N_ + n0 + nl) * 16 + (c0 >> 5)] = word;
        }
        __syncthreads();
    }
}

// ---------------------------------------------------------------------------
// List decode from 16 mask words (deterministic, ascending c). 128 threads.
// ---------------------------------------------------------------------------
__device__ __forceinline__ int decode_list(const uint32_t* __restrict__ gmask,
                                           uint16_t* list, uint32_t* maskw,
                                           int* basew, int* cntp)
{
    int tid = threadIdx.x, warp = tid >> 5, lane = tid & 31;
    if (tid < 16) maskw[tid] = gmask[tid];
    __syncthreads();
    if (tid == 0) {
        int s = 0;
        #pragma unroll
        for (int ci = 0; ci < 16; ci++) { basew[ci] = s; s += __popc(maskw[ci]); }
        *cntp = s;
    }
    __syncthreads();
    #pragma unroll
    for (int ci = warp; ci < 16; ci += 4) {
        uint32_t m = maskw[ci];
        if (m & (1u << lane))
            list[basew[ci] + __popc(m & ((1u << lane) - 1u))] = (uint16_t)(ci * 32 + lane);
    }
    __syncthreads();
    return *cntp;
}

// ---------------------------------------------------------------------------
// Pack 4 spike bits/thread into 16 words across 128 threads, store to gmem.
// Thread tid owns channels 4tid..4tid+3 -> bit 4*(tid&7)+j of word tid>>3.
// ---------------------------------------------------------------------------
__device__ __forceinline__ void store_bits(uint32_t* __restrict__ grow,
                                           uint32_t nib, int tid, int lane)
{
    uint32_t contrib = nib << (4 * (lane & 7));
    contrib |= __shfl_xor_sync(FULLW, contrib, 1);
    contrib |= __shfl_xor_sync(FULLW, contrib, 2);
    contrib |= __shfl_xor_sync(FULLW, contrib, 4);
    if ((lane & 7) == 0) grow[tid >> 3] = contrib;
}

// ---------------------------------------------------------------------------
// Fused Q/K/V gather-GEMM + BN + LIF (vth=1) -> spike BITS.
// Block = (b, n); loops t with LIF state in registers.
// ---------------------------------------------------------------------------
__global__ __launch_bounds__(128)
void gather_qkv_lif_kernel(const float* __restrict__ qg, const float* __restrict__ qb,
                           const float* __restrict__ qm, const float* __restrict__ qv,
                           const float* __restrict__ kg, const float* __restrict__ kb,
                           const float* __restrict__ km, const float* __restrict__ kv,
                           const float* __restrict__ vg, const float* __restrict__ vb,
                           const float* __restrict__ vm, const float* __restrict__ vv)
{
    int b = blockIdx.y, n = blockIdx.x;
    int tid = threadIdx.x, lane = tid & 31;

    __shared__ uint16_t list[C_];
    __shared__ uint32_t maskw[16];
    __shared__ int basew[16];
    __shared__ int cnt;

    const float4* Wq4 = (const float4*)(g_wt + 0 * (size_t)CC);
    const float4* Wk4 = (const float4*)(g_wt + 1 * (size_t)CC);
    const float4* Wv4 = (const float4*)(g_wt + 2 * (size_t)CC);

    float4 qs_c, qs_h, ks_c, ks_h, vs_c, vs_h;
    {
        float4 g = ((const float4*)qg)[tid], bb = ((const float4*)qb)[tid];
        float4 m = ((const float4*)qm)[tid], v = ((const float4*)qv)[tid];
        qs_c.x = g.x * rsqrtf(v.x + EPS_); qs_h.x = bb.x - m.x * qs_c.x;
        qs_c.y = g.y * rsqrtf(v.y + EPS_); qs_h.y = bb.y - m.y * qs_c.y;
        qs_c.z = g.z * rsqrtf(v.z + EPS_); qs_h.z = bb.z - m.z * qs_c.z;
        qs_c.w = g.w * rsqrtf(v.w + EPS_); qs_h.w = bb.w - m.w * qs_c.w;
    }
    {
        float4 g = ((const float4*)kg)[tid], bb = ((const float4*)kb)[tid];
        float4 m = ((const float4*)km)[tid], v = ((const float4*)kv)[tid];
        ks_c.x = g.x * rsqrtf(v.x + EPS_); ks_h.x = bb.x - m.x * ks_c.x;
        ks_c.y = g.y * rsqrtf(v.y + EPS_); ks_h.y = bb.y - m.y * ks_c.y;
        ks_c.z = g.z * rsqrtf(v.z + EPS_); ks_h.z = bb.z - m.z * ks_c.z;
        ks_c.w = g.w * rsqrtf(v.w + EPS_); ks_h.w = bb.w - m.w * ks_c.w;
    }
    {
        float4 g = ((const float4*)vg)[tid], bb = ((const float4*)vb)[tid];
        float4 m = ((const float4*)vm)[tid], v = ((const float4*)vv)[tid];
        vs_c.x = g.x * rsqrtf(v.x + EPS_); vs_h.x = bb.x - m.x * vs_c.x;
        vs_c.y = g.y * rsqrtf(v.y + EPS_); vs_h.y = bb.y - m.y * vs_c.y;
        vs_c.z = g.z * rsqrtf(v.z + EPS_); vs_h.z = bb.z - m.z * vs_c.z;
        vs_c.w = g.w * rsqrtf(v.w + EPS_); vs_h.w = bb.w - m.w * vs_c.w;
    }

    float4 mq = {0.f,0.f,0.f,0.f}, mk = mq, mv = mq;

    for (int t = 0; t < T_; t++) {
        int tb = t * B_ + b;
        size_t rbase = ((size_t)tb * N_ + n) * 16;
        int count = decode_list(g_bx + rbase, list, maskw, basew, &cnt);

        float4 aq = {0.f,0.f,0.f,0.f}, ak = aq, av = aq;
        for (int i = 0; i < count; i++) {
            int c = list[i];
            float4 wq = Wq4[(size_t)c * 128 + tid];
            float4 wk = Wk4[(size_t)c * 128 + tid];
            float4 wv = Wv4[(size_t)c * 128 + tid];
            aq.x += wq.x; aq.y += wq.y; aq.z += wq.z; aq.w += wq.w;
            ak.x += wk.x; ak.y += wk.y; ak.z += wk.z; ak.w += wk.w;
            av.x += wv.x; av.y += wv.y; av.z += wv.z; av.w += wv.w;
        }

        // q: BN + LIF -> bits
        {
            float y0 = aq.x * qs_c.x + qs_h.x, y1 = aq.y * qs_c.y + qs_h.y;
            float y2 = aq.z * qs_c.z + qs_h.z, y3 = aq.w * qs_c.w + qs_h.w;
            uint32_t nib = 0;
            mq.x = fmaf(y0 - mq.x, 0.5f, mq.x); nib |= (mq.x >= 1.f) ? 1u : 0u; mq.x = (mq.x >= 1.f) ? 0.f : mq.x;
            mq.y = fmaf(y1 - mq.y, 0.5f, mq.y); nib |= (mq.y >= 1.f) ? 2u : 0u; mq.y = (mq.y >= 1.f) ? 0.f : mq.y;
            mq.z = fmaf(y2 - mq.z, 0.5f, mq.z); nib |= (mq.z >= 1.f) ? 4u : 0u; mq.z = (mq.z >= 1.f) ? 0.f : mq.z;
            mq.w = fmaf(y3 - mq.w, 0.5f, mq.w); nib |= (mq.w >= 1.f) ? 8u : 0u; mq.w = (mq.w >= 1.f) ? 0.f : mq.w;
            store_bits(g_bq + rbase, nib, tid, lane);
        }
        // k
        {
            float y0 = ak.x * ks_c.x + ks_h.x, y1 = ak.y * ks_c.y + ks_h.y;
            float y2 = ak.z * ks_c.z + ks_h.z, y3 = ak.w * ks_c.w + ks_h.w;
            uint32_t nib = 0;
            mk.x = fmaf(y0 - mk.x, 0.5f, mk.x); nib |= (mk.x >= 1.f) ? 1u : 0u; mk.x = (mk.x >= 1.f) ? 0.f : mk.x;
            mk.y = fmaf(y1 - mk.y, 0.5f, mk.y); nib |= (mk.y >= 1.f) ? 2u : 0u; mk.y = (mk.y >= 1.f) ? 0.f : mk.y;
            mk.z = fmaf(y2 - mk.z, 0.5f, mk.z); nib |= (mk.z >= 1.f) ? 4u : 0u; mk.z = (mk.z >= 1.f) ? 0.f : mk.z;
            mk.w = fmaf(y3 - mk.w, 0.5f, mk.w); nib |= (mk.w >= 1.f) ? 8u : 0u; mk.w = (mk.w >= 1.f) ? 0.f : mk.w;
            store_bits(g_bk + rbase, nib, tid, lane);
        }
        // v
        {
            float y0 = av.x * vs_c.x + vs_h.x, y1 = av.y * vs_c.y + vs_h.y;
            float y2 = av.z * vs_c.z + vs_h.z, y3 = av.w * vs_c.w + vs_h.w;
            uint32_t nib = 0;
            mv.x = fmaf(y0 - mv.x, 0.5f, mv.x); nib |= (mv.x >= 1.f) ? 1u : 0u; mv.x = (mv.x >= 1.f) ? 0.f : mv.x;
            mv.y = fmaf(y1 - mv.y, 0.5f, mv.y); nib |= (mv.y >= 1.f) ? 2u : 0u; mv.y = (mv.y >= 1.f) ? 0.f : mv.y;
            mv.z = fmaf(y2 - mv.z, 0.5f, mv.z); nib |= (mv.z >= 1.f) ? 4u : 0u; mv.z = (mv.z >= 1.f) ? 0.f : mv.z;
            mv.w = fmaf(y3 - mv.w, 0.5f, mv.w); nib |= (mv.w >= 1.f) ? 8u : 0u; mv.w = (mv.w >= 1.f) ? 0.f : mv.w;
            store_bits(g_bv + rbase, nib, tid, lane);
        }
    }
}

// ---------------------------------------------------------------------------
// 32x32 bit-transpose: g_bk/g_bv [tb][n][c-word] -> g_mk/g_mv [tb][c][n-word]
// One warp per (tb, cw, nw) tile; 8 warps/block.
// ---------------------------------------------------------------------------
__global__ __launch_bounds__(256)
void bit_transpose_kernel()
{
    int wg = blockIdx.x * 8 + (threadIdx.x >> 5);   // 0 .. 8191
    int lane = threadIdx.x & 31;
    int tb = wg >> 9;                // 512 tiles per tb (16 cw * 32 nw)
    int rem = wg & 511;
    int cw = rem >> 5, nw = rem & 31;

    uint32_t wk = g_bk[((size_t)tb * N_ + nw * 32 + lane) * 16 + cw];
    uint32_t wv = g_bv[((size_t)tb * N_ + nw * 32 + lane) * 16 + cw];
    uint32_t myk = 0, myv = 0;
    #pragma unroll
    for (int j = 0; j < 32; j++) {
        uint32_t bk_ = __ballot_sync(FULLW, (wk >> j) & 1u);
        uint32_t bv_ = __ballot_sync(FULLW, (wv >> j) & 1u);
        if (lane == j) { myk = bk_; myv = bv_; }
    }
    g_mk[((size_t)tb * C_ + cw * 32 + lane) * 32 + nw] = myk;
    g_mv[((size_t)tb * C_ + cw * 32 + lane) * 32 + nw] = myv;
}

// ---------------------------------------------------------------------------
// KV[e][dd] = 0.125 * popc-sum(maskK_e & maskV_dd)  per (tb,h) — exact.
// ---------------------------------------------------------------------------
__global__ __launch_bounds__(256)
void kv_popc_kernel()
{
    int idx = blockIdx.x;                   // tb*8 + h
    int tb = idx >> 3, h = idx & 7;
    float* KVb = g_kv + (size_t)idx * HD_ * HD_;

    __shared__ uint32_t MK[64][32];
    __shared__ uint32_t MV[64][32];

    int tid = threadIdx.x;
    for (int i = tid; i < 64 * 32; i += 256) {
        int e = i >> 5, w = i & 31;
        MK[e][w] = g_mk[((size_t)tb * C_ + h * HD_ + e) * 32 + w];
        MV[e][w] = g_mv[((size_t)tb * C_ + h * HD_ + e) * 32 + w];
    }
    __syncthreads();

    #pragma unroll
    for (int r = 0; r < 16; r++) {
        int p = r * 256 + tid;              // 0..4095
        int e = p >> 6, dd = p & 63;
        int s = 0;
        #pragma unroll
        for (int w = 0; w < 32; w++)
            s += __popc(MK[e][w] & MV[dd][w]);
        KVb[(size_t)e * HD_ + dd] = (float)s * 0.125f;
    }
}

// ---------------------------------------------------------------------------
// o_pre[tb][n][h64+dd] = sum_{e: qbit} KV[e][dd] -> g_y
// q read as 2 bit-words per (n,h).
// ---------------------------------------------------------------------------
__global__ __launch_bounds__(128)
void qkv_apply_kernel()
{
    int idx = blockIdx.y;                   // tb*8 + h
    int tb = idx >> 3, h = idx & 7;
    int n = blockIdx.x * 128 + threadIdx.x;
    const float* KVb = g_kv + (size_t)idx * HD_ * HD_;
    float* orow = g_y + ((size_t)tb * N_ + n) * C_ + h * HD_;

    __shared__ __align__(16) float KVs[HD_ * HD_];
    for (int i = threadIdx.x; i < HD_ * HD_; i += 128) KVs[i] = KVb[i];
    __syncthreads();

    uint32_t qw0 = g_bq[((size_t)tb * N_ + n) * 16 + 2 * h];
    uint32_t qw1 = g_bq[((size_t)tb * N_ + n) * 16 + 2 * h + 1];

    float acc[64];
    #pragma unroll
    for (int d = 0; d < 64; d++) acc[d] = 0.f;

    #pragma unroll 8
    for (int e = 0; e < 32; e++) {
        if ((qw0 >> e) & 1u) {
            const float4* row = (const float4*)(KVs + e * 64);
            #pragma unroll
            for (int dq = 0; dq < 16; dq++) {
                float4 kvv = row[dq];
                acc[dq*4+0] += kvv.x; acc[dq*4+1] += kvv.y;
                acc[dq*4+2] += kvv.z; acc[dq*4+3] += kvv.w;
            }
        }
    }
    #pragma unroll 8
    for (int e = 0; e < 32; e++) {
        if ((qw1 >> e) & 1u) {
            const float4* row = (const float4*)(KVs + (32 + e) * 64);
            #pragma unroll
            for (int dq = 0; dq < 16; dq++) {
                float4 kvv = row[dq];
                acc[dq*4+0] += kvv.x; acc[dq*4+1] += kvv.y;
                acc[dq*4+2] += kvv.z; acc[dq*4+3] += kvv.w;
            }
        }
    }
    #pragma unroll
    for (int q = 0; q < 16; q++) {
        float4 o = {acc[q*4+0], acc[q*4+1], acc[q*4+2], acc[q*4+3]};
        ((float4*)orow)[q] = o;
    }
}

// ---------------------------------------------------------------------------
// Fused attn-LIF (vth=0.5) + projection gather + bias + BN -> g_ot [tb][n][c]
// ---------------------------------------------------------------------------
__global__ __launch_bounds__(128)
void gather_proj_lif_kernel(const float* __restrict__ bp,
                            const float* __restrict__ pg, const float* __restrict__ pb,
                            const float* __restrict__ pm, const float* __restrict__ pv)
{
    int b = blockIdx.y, n = blockIdx.x;
    int tid = threadIdx.x, warp = tid >> 5, lane = tid & 31;

    __shared__ float srow[C_];
    __shared__ uint16_t list[C_];
    __shared__ uint32_t maskw[16];
    __shared__ int basew[16];
    __shared__ int cnt;

    const float4* Wp4 = (const float4*)(g_wt + 3 * (size_t)CC);

    float4 sc, sh;
    {
        float4 g = ((const float4*)pg)[tid], bb = ((const float4*)pb)[tid];
        float4 m = ((const float4*)pm)[tid], v = ((const float4*)pv)[tid];
        float4 bi = ((const float4*)bp)[tid];
        sc.x = g.x * rsqrtf(v.x + EPS_); sh.x = bb.x + (bi.x - m.x) * sc.x;
        sc.y = g.y * rsqrtf(v.y + EPS_); sh.y = bb.y + (bi.y - m.y) * sc.y;
        sc.z = g.z * rsqrtf(v.z + EPS_); sh.z = bb.z + (bi.z - m.z) * sc.z;
        sc.w = g.w * rsqrtf(v.w + EPS_); sh.w = bb.w + (bi.w - m.w) * sc.w;
    }

    float4 mo = {0.f, 0.f, 0.f, 0.f};

    for (int t = 0; t < T_; t++) {
        int tb = t * B_ + b;
        float4 y = ((const float4*)(g_y + ((size_t)tb * N_ + n) * C_))[tid];
        float4 s4;
        mo.x = fmaf(y.x - mo.x, 0.5f, mo.x); s4.x = (mo.x >= 0.5f) ? 1.f : 0.f; mo.x = (mo.x >= 0.5f) ? 0.f : mo.x;
        mo.y = fmaf(y.y - mo.y, 0.5f, mo.y); s4.y = (mo.y >= 0.5f) ? 1.f : 0.f; mo.y = (mo.y >= 0.5f) ? 0.f : mo.y;
        mo.z = fmaf(y.z - mo.z, 0.5f, mo.z); s4.z = (mo.z >= 0.5f) ? 1.f : 0.f; mo.z = (mo.z >= 0.5f) ? 0.f : mo.z;
        mo.w = fmaf(y.w - mo.w, 0.5f, mo.w); s4.w = (mo.w >= 0.5f) ? 1.f : 0.f; mo.w = (mo.w >= 0.5f) ? 0.f : mo.w;
        ((float4*)srow)[tid] = s4;
        __syncthreads();

        // ballot-based list build from srow
        #pragma unroll
        for (int ci = warp; ci < 16; ci += 4) {
            uint32_t m = __ballot_sync(FULLW, srow[ci * 32 + lane] != 0.f);
            if (lane == 0) maskw[ci] = m;
        }
        __syncthreads();
        if (tid == 0) {
            int s = 0;
            #pragma unroll
            for (int ci = 0; ci < 16; ci++) { basew[ci] = s; s += __popc(maskw[ci]); }
            cnt = s;
        }
        __syncthreads();
        #pragma unroll
        for (int ci = warp; ci < 16; ci += 4) {
            uint32_t m = maskw[ci];
            if (m & (1u << lane))
                list[basew[ci] + __popc(m & ((1u << lane) - 1u))] = (uint16_t)(ci * 32 + lane);
        }
        __syncthreads();
        int count = cnt;

        float4 ap = {0.f, 0.f, 0.f, 0.f};
        for (int i = 0; i < count; i++) {
            int c = list[i];
            float4 wp = Wp4[(size_t)c * 128 + tid];
            ap.x += wp.x; ap.y += wp.y; ap.z += wp.z; ap.w += wp.w;
        }

        float4 o;
        o.x = ap.x * sc.x + sh.x;
        o.y = ap.y * sc.y + sh.y;
        o.z = ap.z * sc.z + sh.z;
        o.w = ap.w * sc.w + sh.w;
        ((float4*)(g_ot + ((size_t)tb * N_ + n) * C_))[tid] = o;
        __syncthreads();
    }
}

// ---------------------------------------------------------------------------
// Final transpose: g_ot [tb][n][c] -> out [tb][c][n]
// ---------------------------------------------------------------------------
__global__ __launch_bounds__(256)
void transpose_out_kernel(float* __restrict__ out)
{
    int tb = blockIdx.z;
    int n0 = blockIdx.y * 32;
    int c0 = blockIdx.x * 32;
    int tx = threadIdx.x & 31, ty = threadIdx.x >> 5;
    __shared__ float s[32][33];
    const float* src = g_ot + (size_t)tb * N_ * C_;
    float* dst = out + (size_t)tb * C_ * N_;
    #pragma unroll
    for (int r = 0; r < 4; r++)
        s[ty + 8 * r][tx] = src[(size_t)(n0 + ty + 8 * r) * C_ + c0 + tx];
    __syncthreads();
    #pragma unroll
    for (int r = 0; r < 4; r++)
        dst[(size_t)(c0 + ty + 8 * r) * N_ + n0 + tx] = s[tx][ty + 8 * r];
}

// ---------------------------------------------------------------------------
// Launch
// ---------------------------------------------------------------------------
extern "C" void kernel_launch(void* const* d_in, const int* in_sizes, int n_in,
                              void* d_out, int out_size)
{
    const float* x   = (const float*)d_in[0];
    const float* Wq  = (const float*)d_in[1];
    const float* q_g = (const float*)d_in[2];
    const float* q_b = (const float*)d_in[3];
    const float* q_m = (const float*)d_in[4];
    const float* q_v = (const float*)d_in[5];
    const float* Wk  = (const float*)d_in[6];
    const float* k_g = (const float*)d_in[7];
    const float* k_b = (const float*)d_in[8];
    const float* k_m = (const float*)d_in[9];
    const float* k_v = (const float*)d_in[10];
    const float* Wv  = (const float*)d_in[11];
    const float* v_g = (const float*)d_in[12];
    const float* v_b = (const float*)d_in[13];
    const float* v_m = (const float*)d_in[14];
    const float* v_v = (const float*)d_in[15];
    const float* Wp  = (const float*)d_in[16];
    const float* bp  = (const float*)d_in[17];
    const float* p_g = (const float*)d_in[18];
    const float* p_b = (const float*)d_in[19];
    const float* p_m = (const float*)d_in[20];
    const float* p_v = (const float*)d_in[21];
    float* out = (float*)d_out;

    prep_wt_kernel<<<dim3(C_ / 32, C_ / 32, 4), 256>>>(Wq, Wk, Wv, Wp);
    lif_in_bits_kernel<<<dim3(N_ / 32, C_ / 32, B_), 256>>>(x);
    gather_qkv_lif_kernel<<<dim3(N_, B_), 128>>>(
        q_g, q_b, q_m, q_v, k_g, k_b, k_m, k_v, v_g, v_b, v_m, v_v);
    bit_transpose_kernel<<<TBAT * 512 / 8, 256>>>();
    kv_popc_kernel<<<TBAT * NH_, 256>>>();
    qkv_apply_kernel<<<dim3(N_ / 128, TBAT * NH_), 128>>>();
    gather_proj_lif_kernel<<<dim3(N_, B_), 128>>>(bp, p_g, p_b, p_m, p_v);
    transpose_out_kernel<<<dim3(C_ / 32, N_ / 32, TBAT), 256>>>(out);
}

// round 12
// speedup vs baseline: 23.9226x; 1.1263x over previous
#include <cuda_runtime.h>
#include <cstdint>

// ---------------------------------------------------------------------------
// Problem constants
// ---------------------------------------------------------------------------
#define T_  4
#define B_  4
#define C_  512
#define N_  1024          // H*W
#define NH_ 8
#define HD_ 64
#define TBAT (T_*B_)
#define BCN  (B_*C_*N_)   // 2,097,152
#define CC   (C_*C_)
#define EPS_ 1e-5f
#define FULLW 0xffffffffu

// ---------------------------------------------------------------------------
// Device scratch (static — no allocation anywhere)
// Spikes live as bitmasks: row layout [tb][n][16 c-words] (bit = c&31).
// ---------------------------------------------------------------------------
__device__ float    g_wt[4 * CC];          // W^T per branch: [w][c][d]
__device__ uint32_t g_bx[TBAT * N_ * 16];  // input spike bits
__device__ uint32_t g_bq[TBAT * N_ * 16];  // q spike bits
__device__ uint32_t g_bk[TBAT * N_ * 16];  // k spike bits
__device__ uint32_t g_bv[TBAT * N_ * 16];  // v spike bits
__device__ uint32_t g_mk[TBAT * C_ * 32];  // k bits reoriented: [tb][c][32 n-words]
__device__ uint32_t g_mv[TBAT * C_ * 32];
__device__ float    g_ot[T_ * BCN];        // proj output [tb][n][c]
__device__ float    g_kv[TBAT * NH_ * HD_ * HD_];  // [tb*8+h][e][dd], carries x0.125

// ---------------------------------------------------------------------------
// Weight transpose (all 4 branches): W[d][c] -> g_wt[w][c][d]
// ---------------------------------------------------------------------------
__global__ __launch_bounds__(256)
void prep_wt_kernel(const float* __restrict__ Wq, const float* __restrict__ Wk,
                    const float* __restrict__ Wv, const float* __restrict__ Wp)
{
    int w = blockIdx.z;
    const float* src = (w == 0) ? Wq : (w == 1) ? Wk : (w == 2) ? Wv : Wp;
    float* dst = g_wt + (size_t)w * CC;
    int d0 = blockIdx.y * 32, c0 = blockIdx.x * 32;
    int tx = threadIdx.x & 31, ty = threadIdx.x >> 5;
    __shared__ float s[32][33];
    #pragma unroll
    for (int r = 0; r < 4; r++)
        s[ty + 8 * r][tx] = src[(size_t)(d0 + ty + 8 * r) * C_ + c0 + tx];
    __syncthreads();
    #pragma unroll
    for (int r = 0; r < 4; r++)
        dst[(size_t)(c0 + ty + 8 * r) * C_ + d0 + tx] = s[tx][ty + 8 * r];
}

// ---------------------------------------------------------------------------
// Input LIF -> spike BITS.  x fp32 [t,b,c,n] -> g_bx[tb][n][c-word], vth=1.
// ---------------------------------------------------------------------------
__global__ __launch_bounds__(256)
void lif_in_bits_kernel(const float* __restrict__ x)
{
    int b  = blockIdx.z;
    int c0 = blockIdx.y * 32;
    int n0 = blockIdx.x * 32;
    int tx = threadIdx.x & 31, ty = threadIdx.x >> 5;
    int warp = threadIdx.x >> 5, lane = threadIdx.x & 31;
    __shared__ float s[32][33];
    float v[4] = {0.f, 0.f, 0.f, 0.f};

    for (int t = 0; t < T_; t++) {
        #pragma unroll
        for (int r = 0; r < 4; r++) {
            int c = c0 + ty + 8 * r;
            float xv = x[(((size_t)t * B_ + b) * C_ + c) * (size_t)N_ + n0 + tx];
            float vv = v[r];
            vv = fmaf(xv - vv, 0.5f, vv);
            float sp = (vv >= 1.0f) ? 1.f : 0.f;
            v[r] = (vv >= 1.0f) ? 0.f : vv;
            s[ty + 8 * r][tx] = sp;
        }
        __syncthreads();
        int tb = t * B_ + b;
        #pragma unroll
        for (int r = 0; r < 4; r++) {
            int nl = warp * 4 + r;
            uint32_t word = __ballot_sync(FULLW, s[lane][nl] != 0.f);
            if (lane == 0)
                g_bx[((size_t)tb * N_ + n0 + nl) * 16 + (c0 >> 5)] = word;
        }
        __syncthreads();
    }
}

// ---------------------------------------------------------------------------
// List decode from 16 mask words (deterministic, ascending c). 128 threads.
// ---------------------------------------------------------------------------
__device__ __forceinline__ int decode_list(const uint32_t* __restrict__ gmask,
                                           uint16_t* list, uint32_t* maskw,
                                           int* basew, int* cntp)
{
    int tid = threadIdx.x, warp = tid >> 5, lane = tid & 31;
    if (tid < 16) maskw[tid] = gmask[tid];
    __syncthreads();
    if (tid == 0) {
        int s = 0;
        #pragma unroll
        for (int ci = 0; ci < 16; ci++) { basew[ci] = s; s += __popc(maskw[ci]); }
        *cntp = s;
    }
    __syncthreads();
    #pragma unroll
    for (int ci = warp; ci < 16; ci += 4) {
        uint32_t m = maskw[ci];
        if (m & (1u << lane))
            list[basew[ci] + __popc(m & ((1u << lane) - 1u))] = (uint16_t)(ci * 32 + lane);
    }
    __syncthreads();
    return *cntp;
}

// ---------------------------------------------------------------------------
// Pack 4 spike bits/thread into 16 words across 128 threads, store to gmem.
// ---------------------------------------------------------------------------
__device__ __forceinline__ void store_bits(uint32_t* __restrict__ grow,
                                           uint32_t nib, int tid, int lane)
{
    uint32_t contrib = nib << (4 * (lane & 7));
    contrib |= __shfl_xor_sync(FULLW, contrib, 1);
    contrib |= __shfl_xor_sync(FULLW, contrib, 2);
    contrib |= __shfl_xor_sync(FULLW, contrib, 4);
    if ((lane & 7) == 0) grow[tid >> 3] = contrib;
}

// ---------------------------------------------------------------------------
// Fused Q/K/V gather-GEMM + BN + LIF (vth=1) -> spike BITS.
// ---------------------------------------------------------------------------
__global__ __launch_bounds__(128)
void gather_qkv_lif_kernel(const float* __restrict__ qg, const float* __restrict__ qb,
                           const float* __restrict__ qm, const float* __restrict__ qv,
                           const float* __restrict__ kg, const float* __restrict__ kb,
                           const float* __restrict__ km, const float* __restrict__ kv,
                           const float* __restrict__ vg, const float* __restrict__ vb,
                           const float* __restrict__ vm, const float* __restrict__ vv)
{
    int b = blockIdx.y, n = blockIdx.x;
    int tid = threadIdx.x, lane = tid & 31;

    __shared__ uint16_t list[C_];
    __shared__ uint32_t maskw[16];
    __shared__ int basew[16];
    __shared__ int cnt;

    const float4* Wq4 = (const float4*)(g_wt + 0 * (size_t)CC);
    const float4* Wk4 = (const float4*)(g_wt + 1 * (size_t)CC);
    const float4* Wv4 = (const float4*)(g_wt + 2 * (size_t)CC);

    float4 qs_c, qs_h, ks_c, ks_h, vs_c, vs_h;
    {
        float4 g = ((const float4*)qg)[tid], bb = ((const float4*)qb)[tid];
        float4 m = ((const float4*)qm)[tid], v = ((const float4*)qv)[tid];
        qs_c.x = g.x * rsqrtf(v.x + EPS_); qs_h.x = bb.x - m.x * qs_c.x;
        qs_c.y = g.y * rsqrtf(v.y + EPS_); qs_h.y = bb.y - m.y * qs_c.y;
        qs_c.z = g.z * rsqrtf(v.z + EPS_); qs_h.z = bb.z - m.z * qs_c.z;
        qs_c.w = g.w * rsqrtf(v.w + EPS_); qs_h.w = bb.w - m.w * qs_c.w;
    }
    {
        float4 g = ((const float4*)kg)[tid], bb = ((const float4*)kb)[tid];
        float4 m = ((const float4*)km)[tid], v = ((const float4*)kv)[tid];
        ks_c.x = g.x * rsqrtf(v.x + EPS_); ks_h.x = bb.x - m.x * ks_c.x;
        ks_c.y = g.y * rsqrtf(v.y + EPS_); ks_h.y = bb.y - m.y * ks_c.y;
        ks_c.z = g.z * rsqrtf(v.z + EPS_); ks_h.z = bb.z - m.z * ks_c.z;
        ks_c.w = g.w * rsqrtf(v.w + EPS_); ks_h.w = bb.w - m.w * ks_c.w;
    }
    {
        float4 g = ((const float4*)vg)[tid], bb = ((const float4*)vb)[tid];
        float4 m = ((const float4*)vm)[tid], v = ((const float4*)vv)[tid];
        vs_c.x = g.x * rsqrtf(v.x + EPS_); vs_h.x = bb.x - m.x * vs_c.x;
        vs_c.y = g.y * rsqrtf(v.y + EPS_); vs_h.y = bb.y - m.y * vs_c.y;
        vs_c.z = g.z * rsqrtf(v.z + EPS_); vs_h.z = bb.z - m.z * vs_c.z;
        vs_c.w = g.w * rsqrtf(v.w + EPS_); vs_h.w = bb.w - m.w * vs_c.w;
    }

    float4 mq = {0.f,0.f,0.f,0.f}, mk = mq, mv = mq;

    for (int t = 0; t < T_; t++) {
        int tb = t * B_ + b;
        size_t rbase = ((size_t)tb * N_ + n) * 16;
        int count = decode_list(g_bx + rbase, list, maskw, basew, &cnt);

        float4 aq = {0.f,0.f,0.f,0.f}, ak = aq, av = aq;
        for (int i = 0; i < count; i++) {
            int c = list[i];
            float4 wq = Wq4[(size_t)c * 128 + tid];
            float4 wk = Wk4[(size_t)c * 128 + tid];
            float4 wv = Wv4[(size_t)c * 128 + tid];
            aq.x += wq.x; aq.y += wq.y; aq.z += wq.z; aq.w += wq.w;
            ak.x += wk.x; ak.y += wk.y; ak.z += wk.z; ak.w += wk.w;
            av.x += wv.x; av.y += wv.y; av.z += wv.z; av.w += wv.w;
        }

        {
            float y0 = aq.x * qs_c.x + qs_h.x, y1 = aq.y * qs_c.y + qs_h.y;
            float y2 = aq.z * qs_c.z + qs_h.z, y3 = aq.w * qs_c.w + qs_h.w;
            uint32_t nib = 0;
            mq.x = fmaf(y0 - mq.x, 0.5f, mq.x); nib |= (mq.x >= 1.f) ? 1u : 0u; mq.x = (mq.x >= 1.f) ? 0.f : mq.x;
            mq.y = fmaf(y1 - mq.y, 0.5f, mq.y); nib |= (mq.y >= 1.f) ? 2u : 0u; mq.y = (mq.y >= 1.f) ? 0.f : mq.y;
            mq.z = fmaf(y2 - mq.z, 0.5f, mq.z); nib |= (mq.z >= 1.f) ? 4u : 0u; mq.z = (mq.z >= 1.f) ? 0.f : mq.z;
            mq.w = fmaf(y3 - mq.w, 0.5f, mq.w); nib |= (mq.w >= 1.f) ? 8u : 0u; mq.w = (mq.w >= 1.f) ? 0.f : mq.w;
            store_bits(g_bq + rbase, nib, tid, lane);
        }
        {
            float y0 = ak.x * ks_c.x + ks_h.x, y1 = ak.y * ks_c.y + ks_h.y;
            float y2 = ak.z * ks_c.z + ks_h.z, y3 = ak.w * ks_c.w + ks_h.w;
            uint32_t nib = 0;
            mk.x = fmaf(y0 - mk.x, 0.5f, mk.x); nib |= (mk.x >= 1.f) ? 1u : 0u; mk.x = (mk.x >= 1.f) ? 0.f : mk.x;
            mk.y = fmaf(y1 - mk.y, 0.5f, mk.y); nib |= (mk.y >= 1.f) ? 2u : 0u; mk.y = (mk.y >= 1.f) ? 0.f : mk.y;
            mk.z = fmaf(y2 - mk.z, 0.5f, mk.z); nib |= (mk.z >= 1.f) ? 4u : 0u; mk.z = (mk.z >= 1.f) ? 0.f : mk.z;
            mk.w = fmaf(y3 - mk.w, 0.5f, mk.w); nib |= (mk.w >= 1.f) ? 8u : 0u; mk.w = (mk.w >= 1.f) ? 0.f : mk.w;
            store_bits(g_bk + rbase, nib, tid, lane);
        }
        {
            float y0 = av.x * vs_c.x + vs_h.x, y1 = av.y * vs_c.y + vs_h.y;
            float y2 = av.z * vs_c.z + vs_h.z, y3 = av.w * vs_c.w + vs_h.w;
            uint32_t nib = 0;
            mv.x = fmaf(y0 - mv.x, 0.5f, mv.x); nib |= (mv.x >= 1.f) ? 1u : 0u; mv.x = (mv.x >= 1.f) ? 0.f : mv.x;
            mv.y = fmaf(y1 - mv.y, 0.5f, mv.y); nib |= (mv.y >= 1.f) ? 2u : 0u; mv.y = (mv.y >= 1.f) ? 0.f : mv.y;
            mv.z = fmaf(y2 - mv.z, 0.5f, mv.z); nib |= (mv.z >= 1.f) ? 4u : 0u; mv.z = (mv.z >= 1.f) ? 0.f : mv.z;
            mv.w = fmaf(y3 - mv.w, 0.5f, mv.w); nib |= (mv.w >= 1.f) ? 8u : 0u; mv.w = (mv.w >= 1.f) ? 0.f : mv.w;
            store_bits(g_bv + rbase, nib, tid, lane);
        }
    }
}

// ---------------------------------------------------------------------------
// 32x32 bit-transpose: g_bk/g_bv [tb][n][c-word] -> g_mk/g_mv [tb][c][n-word]
// ---------------------------------------------------------------------------
__global__ __launch_bounds__(256)
void bit_transpose_kernel()
{
    int wg = blockIdx.x * 8 + (threadIdx.x >> 5);
    int lane = threadIdx.x & 31;
    int tb = wg >> 9;
    int rem = wg & 511;
    int cw = rem >> 5, nw = rem & 31;

    uint32_t wk = g_bk[((size_t)tb * N_ + nw * 32 + lane) * 16 + cw];
    uint32_t wv = g_bv[((size_t)tb * N_ + nw * 32 + lane) * 16 + cw];
    uint32_t myk = 0, myv = 0;
    #pragma unroll
    for (int j = 0; j < 32; j++) {
        uint32_t bk_ = __ballot_sync(FULLW, (wk >> j) & 1u);
        uint32_t bv_ = __ballot_sync(FULLW, (wv >> j) & 1u);
        if (lane == j) { myk = bk_; myv = bv_; }
    }
    g_mk[((size_t)tb * C_ + cw * 32 + lane) * 32 + nw] = myk;
    g_mv[((size_t)tb * C_ + cw * 32 + lane) * 32 + nw] = myv;
}

// ---------------------------------------------------------------------------
// KV[e][dd] = 0.125 * popc-sum(maskK_e & maskV_dd)  per (tb,h) — exact.
// ---------------------------------------------------------------------------
__global__ __launch_bounds__(256)
void kv_popc_kernel()
{
    int idx = blockIdx.x;
    int tb = idx >> 3, h = idx & 7;
    float* KVb = g_kv + (size_t)idx * HD_ * HD_;

    __shared__ uint32_t MK[64][32];
    __shared__ uint32_t MV[64][32];

    int tid = threadIdx.x;
    for (int i = tid; i < 64 * 32; i += 256) {
        int e = i >> 5, w = i & 31;
        MK[e][w] = g_mk[((size_t)tb * C_ + h * HD_ + e) * 32 + w];
        MV[e][w] = g_mv[((size_t)tb * C_ + h * HD_ + e) * 32 + w];
    }
    __syncthreads();

    #pragma unroll
    for (int r = 0; r < 16; r++) {
        int p = r * 256 + tid;
        int e = p >> 6, dd = p & 63;
        int s = 0;
        #pragma unroll
        for (int w = 0; w < 32; w++)
            s += __popc(MK[e][w] & MV[dd][w]);
        KVb[(size_t)e * HD_ + dd] = (float)s * 0.125f;
    }
}

// ---------------------------------------------------------------------------
// FUSED: attention-apply + attn-LIF (vth=0.5) + projection gather + bias + BN.
// Block = (b, n); loops t. Thread owns c = 4*tid..4*tid+3 (head h = tid>>4).
// o_pre from KV rows selected by q bits (L2-resident); no float intermediate.
// ---------------------------------------------------------------------------
__global__ __launch_bounds__(128)
void attn_proj_lif_kernel(const float* __restrict__ bp,
                          const float* __restrict__ pg, const float* __restrict__ pb,
                          const float* __restrict__ pm, const float* __restrict__ pv)
{
    int b = blockIdx.y, n = blockIdx.x;
    int tid = threadIdx.x, warp = tid >> 5, lane = tid & 31;
    int h = tid >> 4;            // head of this thread's 4 channels
    int q4i = tid & 15;          // float4 index within head row

    __shared__ uint16_t list[C_];
    __shared__ uint32_t maskw[16];
    __shared__ int basew[16];
    __shared__ int cnt;

    const float4* Wp4 = (const float4*)(g_wt + 3 * (size_t)CC);

    float4 sc, sh;
    {
        float4 g = ((const float4*)pg)[tid], bb = ((const float4*)pb)[tid];
        float4 m = ((const float4*)pm)[tid], v = ((const float4*)pv)[tid];
        float4 bi = ((const float4*)bp)[tid];
        sc.x = g.x * rsqrtf(v.x + EPS_); sh.x = bb.x + (bi.x - m.x) * sc.x;
        sc.y = g.y * rsqrtf(v.y + EPS_); sh.y = bb.y + (bi.y - m.y) * sc.y;
        sc.z = g.z * rsqrtf(v.z + EPS_); sh.z = bb.z + (bi.z - m.z) * sc.z;
        sc.w = g.w * rsqrtf(v.w + EPS_); sh.w = bb.w + (bi.w - m.w) * sc.w;
    }

    float4 mo = {0.f, 0.f, 0.f, 0.f};   // attn-LIF membrane

    for (int t = 0; t < T_; t++) {
        int tb = t * B_ + b;
        size_t rbase = ((size_t)tb * N_ + n) * 16;

        // ---- attention apply: sum KV rows over set q bits (ascending e) ----
        uint32_t qw0 = g_bq[rbase + 2 * h];
        uint32_t qw1 = g_bq[rbase + 2 * h + 1];
        const float4* KVb = (const float4*)(g_kv + (size_t)(tb * NH_ + h) * HD_ * HD_);

        float4 a = {0.f, 0.f, 0.f, 0.f};
        uint32_t m = qw0;
        while (m) {
            int e = __ffs(m) - 1; m &= m - 1;
            float4 kvv = KVb[e * 16 + q4i];
            a.x += kvv.x; a.y += kvv.y; a.z += kvv.z; a.w += kvv.w;
        }
        m = qw1;
        while (m) {
            int e = __ffs(m) - 1; m &= m - 1;
            float4 kvv = KVb[(32 + e) * 16 + q4i];
            a.x += kvv.x; a.y += kvv.y; a.z += kvv.z; a.w += kvv.w;
        }

        // ---- attn LIF (vth = 0.5) -> spike nibble ----
        uint32_t nib = 0;
        mo.x = fmaf(a.x - mo.x, 0.5f, mo.x); nib |= (mo.x >= 0.5f) ? 1u : 0u; mo.x = (mo.x >= 0.5f) ? 0.f : mo.x;
        mo.y = fmaf(a.y - mo.y, 0.5f, mo.y); nib |= (mo.y >= 0.5f) ? 2u : 0u; mo.y = (mo.y >= 0.5f) ? 0.f : mo.y;
        mo.z = fmaf(a.z - mo.z, 0.5f, mo.z); nib |= (mo.z >= 0.5f) ? 4u : 0u; mo.z = (mo.z >= 0.5f) ? 0.f : mo.z;
        mo.w = fmaf(a.w - mo.w, 0.5f, mo.w); nib |= (mo.w >= 0.5f) ? 8u : 0u; mo.w = (mo.w >= 0.5f) ? 0.f : mo.w;

        // ---- build maskw in smem via shfl-OR ----
        uint32_t contrib = nib << (4 * (lane & 7));
        contrib |= __shfl_xor_sync(FULLW, contrib, 1);
        contrib |= __shfl_xor_sync(FULLW, contrib, 2);
        contrib |= __shfl_xor_sync(FULLW, contrib, 4);
        if ((lane & 7) == 0) maskw[tid >> 3] = contrib;
        __syncthreads();

        if (tid == 0) {
            int s = 0;
            #pragma unroll
            for (int ci = 0; ci < 16; ci++) { basew[ci] = s; s += __popc(maskw[ci]); }
            cnt = s;
        }
        __syncthreads();
        #pragma unroll
        for (int ci = warp; ci < 16; ci += 4) {
            uint32_t mm = maskw[ci];
            if (mm & (1u << lane))
                list[basew[ci] + __popc(mm & ((1u << lane) - 1u))] = (uint16_t)(ci * 32 + lane);
        }
        __syncthreads();
        int count = cnt;

        // ---- projection gather ----
        float4 ap = {0.f, 0.f, 0.f, 0.f};
        for (int i = 0; i < count; i++) {
            int c = list[i];
            float4 wp = Wp4[(size_t)c * 128 + tid];
            ap.x += wp.x; ap.y += wp.y; ap.z += wp.z; ap.w += wp.w;
        }

        float4 o;
        o.x = ap.x * sc.x + sh.x;
        o.y = ap.y * sc.y + sh.y;
        o.z = ap.z * sc.z + sh.z;
        o.w = ap.w * sc.w + sh.w;
        ((float4*)(g_ot + ((size_t)tb * N_ + n) * C_))[tid] = o;
        __syncthreads();   // protect list/maskw before next t overwrites them
    }
}

// ---------------------------------------------------------------------------
// Final transpose: g_ot [tb][n][c] -> out [tb][c][n]
// ---------------------------------------------------------------------------
__global__ __launch_bounds__(256)
void transpose_out_kernel(float* __restrict__ out)
{
    int tb = blockIdx.z;
    int n0 = blockIdx.y * 32;
    int c0 = blockIdx.x * 32;
    int tx = threadIdx.x & 31, ty = threadIdx.x >> 5;
    __shared__ float s[32][33];
    const float* src = g_ot + (size_t)tb * N_ * C_;
    float* dst = out + (size_t)tb * C_ * N_;
    #pragma unroll
    for (int r = 0; r < 4; r++)
        s[ty + 8 * r][tx] = src[(size_t)(n0 + ty + 8 * r) * C_ + c0 + tx];
    __syncthreads();
    #pragma unroll
    for (int r = 0; r < 4; r++)
        dst[(size_t)(c0 + ty + 8 * r) * N_ + n0 + tx] = s[tx][ty + 8 * r];
}

// ---------------------------------------------------------------------------
// Launch
// ---------------------------------------------------------------------------
extern "C" void kernel_launch(void* const* d_in, const int* in_sizes, int n_in,
                              void* d_out, int out_size)
{
    const float* x   = (const float*)d_in[0];
    const float* Wq  = (const float*)d_in[1];
    const float* q_g = (const float*)d_in[2];
    const float* q_b = (const float*)d_in[3];
    const float* q_m = (const float*)d_in[4];
    const float* q_v = (const float*)d_in[5];
    const float* Wk  = (const float*)d_in[6];
    const float* k_g = (const float*)d_in[7];
    const float* k_b = (const float*)d_in[8];
    const float* k_m = (const float*)d_in[9];
    const float* k_v = (const float*)d_in[10];
    const float* Wv  = (const float*)d_in[11];
    const float* v_g = (const float*)d_in[12];
    const float* v_b = (const float*)d_in[13];
    const float* v_m = (const float*)d_in[14];
    const float* v_v = (const float*)d_in[15];
    const float* Wp  = (const float*)d_in[16];
    const float* bp  = (const float*)d_in[17];
    const float* p_g = (const float*)d_in[18];
    const float* p_b = (const float*)d_in[19];
    const float* p_m = (const float*)d_in[20];
    const float* p_v = (const float*)d_in[21];
    float* out = (float*)d_out;

    prep_wt_kernel<<<dim3(C_ / 32, C_ / 32, 4), 256>>>(Wq, Wk, Wv, Wp);
    lif_in_bits_kernel<<<dim3(N_ / 32, C_ / 32, B_), 256>>>(x);
    gather_qkv_lif_kernel<<<dim3(N_, B_), 128>>>(
        q_g, q_b, q_m, q_v, k_g, k_b, k_m, k_v, v_g, v_b, v_m, v_v);
    bit_transpose_kernel<<<TBAT * 512 / 8, 256>>>();
    kv_popc_kernel<<<TBAT * NH_, 256>>>();
    attn_proj_lif_kernel<<<dim3(N_, B_), 128>>>(bp, p_g, p_b, p_m, p_v);
    transpose_out_kernel<<<dim3(C_ / 32, N_ / 32, TBAT), 256>>>(out);
}